// round 1
// baseline (speedup 1.0000x reference)
#include <cuda_runtime.h>
#include <math.h>

// ---------------------------------------------------------------------------
// SHMA (single-head linear attention) block, fp32.
// B=8, dim=d=512, N=64*64=4096, qkvg channels = 2048.
// ---------------------------------------------------------------------------

#define BATCH 8
#define DIM   512
#define NPIX  4096
#define C4    2048

// Scratch (static device globals; allocation inside kernel_launch is forbidden)
__device__ float g_y[67108864];     // (8, 2048, 4096)  y = qkvg_w @ x
__device__ float g_q[16777216];     // (8, 512, 4096)
__device__ float g_k[16777216];
__device__ float g_v[16777216];
__device__ float g_attn[16777216];  // attn, then o (in place)
__device__ float g_ypre[16777216];  // proj output pre-BN
__device__ float g_vk[2097152];     // (8, 512, 512)
__device__ float g_a1[2048];        // BN1 affine scale
__device__ float g_b1[2048];        // BN1 affine bias
__device__ float g_a2[512];
__device__ float g_b2[512];
__device__ float g_kmean[4096];     // (8, 512)
__device__ float g_z[32768];        // (8, 4096)

// ---------------------------------------------------------------------------
// Tiled SIMT GEMM: C[b] = alpha * A[b] @ B[b] (optionally B stored [N,K] = NT)
// 128x128 tile, K-step 16, 256 threads, 8x8 microtile per thread.
// All M,N multiples of 128; K multiple of 16 (guaranteed by problem shapes).
// ---------------------------------------------------------------------------
template <bool TRANSB, bool ZDIV>
__global__ void __launch_bounds__(256)
gemm_tile(const float* __restrict__ A, const float* __restrict__ B,
          float* __restrict__ C, int M, int N, int K,
          long long sA, long long sB, long long sC,
          float alpha, const float* __restrict__ zbase, int zstride)
{
    const int b = blockIdx.z;
    A += (long long)b * sA;
    B += (long long)b * sB;
    C += (long long)b * sC;

    __shared__ float As[16][132];
    __shared__ float Bs[16][132];

    const int tid = threadIdx.x;
    const int m0 = blockIdx.y * 128;
    const int n0 = blockIdx.x * 128;
    const int tx = tid & 15;   // 0..15 -> n microtile
    const int ty = tid >> 4;   // 0..15 -> m microtile

    float acc[8][8];
#pragma unroll
    for (int i = 0; i < 8; i++)
#pragma unroll
        for (int j = 0; j < 8; j++) acc[i][j] = 0.f;

    const int lr = tid >> 2;         // 0..63 (row within tile)
    const int lk = (tid & 3) * 4;    // 0,4,8,12 (k within step)
    const int bk = tid >> 5;         // 0..7
    const int bn = (tid & 31) * 4;   // 0..124

    for (int k0 = 0; k0 < K; k0 += 16) {
        // Load A tile (transpose into As[k][m])
#pragma unroll
        for (int r = 0; r < 2; r++) {
            int row = lr + r * 64;
            float4 va = *reinterpret_cast<const float4*>(
                &A[(long long)(m0 + row) * K + k0 + lk]);
            As[lk + 0][row] = va.x; As[lk + 1][row] = va.y;
            As[lk + 2][row] = va.z; As[lk + 3][row] = va.w;
        }
        if (TRANSB) {
            // B stored [N, K] row-major: Bs[k][n] = B[n][k]
#pragma unroll
            for (int r = 0; r < 2; r++) {
                int row = lr + r * 64;
                float4 vb = *reinterpret_cast<const float4*>(
                    &B[(long long)(n0 + row) * K + k0 + lk]);
                Bs[lk + 0][row] = vb.x; Bs[lk + 1][row] = vb.y;
                Bs[lk + 2][row] = vb.z; Bs[lk + 3][row] = vb.w;
            }
        } else {
            // B stored [K, N] row-major
#pragma unroll
            for (int r = 0; r < 2; r++) {
                int kk = bk + r * 8;
                float4 vb = *reinterpret_cast<const float4*>(
                    &B[(long long)(k0 + kk) * N + n0 + bn]);
                *reinterpret_cast<float4*>(&Bs[kk][bn]) = vb;
            }
        }
        __syncthreads();

#pragma unroll
        for (int kk = 0; kk < 16; kk++) {
            float a[8], bb[8];
            *reinterpret_cast<float4*>(&a[0]) =
                *reinterpret_cast<const float4*>(&As[kk][ty * 8]);
            *reinterpret_cast<float4*>(&a[4]) =
                *reinterpret_cast<const float4*>(&As[kk][ty * 8 + 4]);
            *reinterpret_cast<float4*>(&bb[0]) =
                *reinterpret_cast<const float4*>(&Bs[kk][tx * 8]);
            *reinterpret_cast<float4*>(&bb[4]) =
                *reinterpret_cast<const float4*>(&Bs[kk][tx * 8 + 4]);
#pragma unroll
            for (int i = 0; i < 8; i++)
#pragma unroll
                for (int j = 0; j < 8; j++) acc[i][j] += a[i] * bb[j];
        }
        __syncthreads();
    }

    float zinv[8];
    if (ZDIV) {
        const float* zp = zbase + (long long)b * zstride + n0 + tx * 8;
#pragma unroll
        for (int j = 0; j < 8; j++) zinv[j] = 1.f / zp[j];
    }

#pragma unroll
    for (int i = 0; i < 8; i++) {
        long long off = (long long)(m0 + ty * 8 + i) * N + n0 + tx * 8;
        float4 o0, o1;
        float v[8];
#pragma unroll
        for (int j = 0; j < 8; j++) {
            v[j] = acc[i][j] * alpha;
            if (ZDIV) v[j] *= zinv[j];
        }
        o0.x = v[0]; o0.y = v[1]; o0.z = v[2]; o0.w = v[3];
        o1.x = v[4]; o1.y = v[5]; o1.z = v[6]; o1.w = v[7];
        *reinterpret_cast<float4*>(&C[off])     = o0;
        *reinterpret_cast<float4*>(&C[off + 4]) = o1;
    }
}

// ---------------------------------------------------------------------------
// Block reduction (two sums)
// ---------------------------------------------------------------------------
__device__ __forceinline__ void blockReduce2(float& s1, float& s2)
{
    __shared__ float sh1[32], sh2[32];
    int lane = threadIdx.x & 31, w = threadIdx.x >> 5;
#pragma unroll
    for (int o = 16; o > 0; o >>= 1) {
        s1 += __shfl_down_sync(0xffffffffu, s1, o);
        s2 += __shfl_down_sync(0xffffffffu, s2, o);
    }
    if (lane == 0) { sh1[w] = s1; sh2[w] = s2; }
    __syncthreads();
    int nw = blockDim.x >> 5;
    if (w == 0) {
        s1 = lane < nw ? sh1[lane] : 0.f;
        s2 = lane < nw ? sh2[lane] : 0.f;
#pragma unroll
        for (int o = 16; o > 0; o >>= 1) {
            s1 += __shfl_down_sync(0xffffffffu, s1, o);
            s2 += __shfl_down_sync(0xffffffffu, s2, o);
        }
    }
}

// ---------------------------------------------------------------------------
// BatchNorm stats -> per-channel affine (a, b): out = a*y + b
// One block per channel; reduce over 8*4096 = 32768 elements.
// ---------------------------------------------------------------------------
__global__ void bn_stats_kernel(const float* __restrict__ y,
                                const float* __restrict__ gamma,
                                const float* __restrict__ beta,
                                float* __restrict__ a, float* __restrict__ bb,
                                int Cdim)
{
    int c = blockIdx.x;
    float s1 = 0.f, s2 = 0.f;
    for (int i = threadIdx.x; i < BATCH * NPIX; i += blockDim.x) {
        int bi = i >> 12, n = i & 4095;
        float v = y[((long long)bi * Cdim + c) * NPIX + n];
        s1 += v; s2 += v * v;
    }
    blockReduce2(s1, s2);
    if (threadIdx.x == 0) {
        const float inv = 1.f / (BATCH * NPIX);
        float mean = s1 * inv;
        float var = s2 * inv - mean * mean;
        float av = gamma[c] * rsqrtf(var + 1e-5f);
        a[c] = av;
        bb[c] = beta[c] - mean * av;
    }
}

// ---------------------------------------------------------------------------
// Materialize q (sigmoid), k (sigmoid), v (affine) from y + BN1 affine.
// Also reduce kmean[b,d]. One block per (b,d) row.
// ---------------------------------------------------------------------------
__global__ void qkv_kernel()
{
    int row = blockIdx.x;            // 0..4095
    int b = row >> 9, d = row & 511;
    long long base = ((long long)b * C4 + d) * NPIX;
    const float* yq = g_y + base;
    const float* yk = yq + (long long)DIM * NPIX;
    const float* yv = yq + 2LL * DIM * NPIX;
    long long ob = ((long long)b * DIM + d) * NPIX;
    float aq = g_a1[d],        bq = g_b1[d];
    float ak = g_a1[d + 512],  bk = g_b1[d + 512];
    float av = g_a1[d + 1024], bv = g_b1[d + 1024];
    float ks = 0.f, dummy = 0.f;
    for (int n = threadIdx.x; n < NPIX; n += blockDim.x) {
        float qv = 1.f / (1.f + expf(-(aq * yq[n] + bq)));
        float kv = 1.f / (1.f + expf(-(ak * yk[n] + bk)));
        float vv = av * yv[n] + bv;
        g_q[ob + n] = qv;
        g_k[ob + n] = kv;
        g_v[ob + n] = vv;
        ks += kv;
    }
    blockReduce2(ks, dummy);
    if (threadIdx.x == 0) g_kmean[row] = ks * (1.f / NPIX);
}

// ---------------------------------------------------------------------------
// z[b,n] = sum_d kmean[b,d]*q[b,d,n] + eps
// ---------------------------------------------------------------------------
__global__ void z_kernel()
{
    __shared__ float skm[512];
    int b = blockIdx.y;
    int n = blockIdx.x * blockDim.x + threadIdx.x;
    for (int i = threadIdx.x; i < 512; i += blockDim.x)
        skm[i] = g_kmean[b * 512 + i];
    __syncthreads();
    const float* qb = g_q + (long long)b * DIM * NPIX + n;
    float acc = 0.f;
#pragma unroll 16
    for (int d = 0; d < 512; d++) acc += skm[d] * qb[(long long)d * NPIX];
    g_z[b * NPIX + n] = acc + 5e-4f;
}

// ---------------------------------------------------------------------------
// RMSNorm over d + attn_norm_w + SiLU(gate) ; in-place on g_attn.
// Gate g = BN1-affine of channels [1536,2048) of g_y (never materialized).
// ---------------------------------------------------------------------------
__global__ void rmsgate_kernel(const float* __restrict__ anw)
{
    __shared__ float sa[512], sb[512], sw[512];
    int b = blockIdx.y;
    int n = blockIdx.x * blockDim.x + threadIdx.x;
    for (int i = threadIdx.x; i < 512; i += blockDim.x) {
        sa[i] = g_a1[1536 + i];
        sb[i] = g_b1[1536 + i];
        sw[i] = anw[i];
    }
    __syncthreads();
    float* ab = g_attn + (long long)b * DIM * NPIX + n;
    const float* yg = g_y + ((long long)b * C4 + 1536) * NPIX + n;
    float ss = 0.f;
#pragma unroll 16
    for (int d = 0; d < 512; d++) {
        float t = ab[(long long)d * NPIX];
        ss += t * t;
    }
    float r = rsqrtf(ss * (1.f / 512.f) + 1e-6f);
#pragma unroll 8
    for (int d = 0; d < 512; d++) {
        float t = ab[(long long)d * NPIX];
        float gv = sa[d] * yg[(long long)d * NPIX] + sb[d];
        float sg = gv / (1.f + expf(-gv));   // silu
        ab[(long long)d * NPIX] = t * r * sw[d] * sg;
    }
}

// ---------------------------------------------------------------------------
// Apply BN2 affine -> d_out (float4 vectorized)
// ---------------------------------------------------------------------------
__global__ void bnapply_kernel(float* __restrict__ out)
{
    long long i = (long long)(blockIdx.x * blockDim.x + threadIdx.x) * 4;
    int c = (int)((i >> 12) & 511);
    float a = g_a2[c], bb = g_b2[c];
    float4 v = *reinterpret_cast<const float4*>(g_ypre + i);
    v.x = a * v.x + bb; v.y = a * v.y + bb;
    v.z = a * v.z + bb; v.w = a * v.w + bb;
    *reinterpret_cast<float4*>(out + i) = v;
}

// ---------------------------------------------------------------------------
extern "C" void kernel_launch(void* const* d_in, const int* in_sizes, int n_in,
                              void* d_out, int out_size)
{
    const float* x          = (const float*)d_in[0];
    const float* qkvg_w     = (const float*)d_in[1];
    const float* qkvg_gamma = (const float*)d_in[2];
    const float* qkvg_beta  = (const float*)d_in[3];
    const float* attn_norm_w= (const float*)d_in[4];
    const float* proj_w     = (const float*)d_in[5];
    const float* proj_gamma = (const float*)d_in[6];
    const float* proj_beta  = (const float*)d_in[7];
    float* out = (float*)d_out;

    float *py, *pq, *pk, *pv, *pattn, *pypre, *pvk, *pa1, *pb1, *pa2, *pb2, *pz;
    cudaGetSymbolAddress((void**)&py,    g_y);
    cudaGetSymbolAddress((void**)&pq,    g_q);
    cudaGetSymbolAddress((void**)&pk,    g_k);
    cudaGetSymbolAddress((void**)&pv,    g_v);
    cudaGetSymbolAddress((void**)&pattn, g_attn);
    cudaGetSymbolAddress((void**)&pypre, g_ypre);
    cudaGetSymbolAddress((void**)&pvk,   g_vk);
    cudaGetSymbolAddress((void**)&pa1,   g_a1);
    cudaGetSymbolAddress((void**)&pb1,   g_b1);
    cudaGetSymbolAddress((void**)&pa2,   g_a2);
    cudaGetSymbolAddress((void**)&pb2,   g_b2);
    cudaGetSymbolAddress((void**)&pz,    g_z);

    const long long sQKV = (long long)DIM * NPIX;       // 2097152
    const long long sY   = (long long)C4 * NPIX;        // 8388608
    const long long sVK  = (long long)DIM * DIM;        // 262144

    // 1) y = qkvg_w @ x    (M=2048, N=4096, K=512), A shared across batches
    gemm_tile<false, false><<<dim3(32, 16, BATCH), 256>>>(
        qkvg_w, x, py, 2048, 4096, 512, 0, sQKV, sY, 1.f, nullptr, 0);

    // 2) BN1 stats -> affine
    bn_stats_kernel<<<2048, 256>>>(py, qkvg_gamma, qkvg_beta, pa1, pb1, 2048);

    // 3) q,k,v materialization + kmean
    qkv_kernel<<<4096, 256>>>();

    // 4) z
    z_kernel<<<dim3(16, BATCH), 256>>>();

    // 5) vk = (v*s) @ (k*s)^T   (NT, M=N=512, K=4096), alpha = scale^2 = 1/4096
    gemm_tile<true, false><<<dim3(4, 4, BATCH), 256>>>(
        pv, pk, pvk, 512, 512, 4096, sQKV, sQKV, sVK, 1.f / 4096.f, nullptr, 0);

    // 6) attn = vk @ q / z   (NN, M=512, N=4096, K=512), z-divide fused
    gemm_tile<false, true><<<dim3(32, 4, BATCH), 256>>>(
        pvk, pq, pattn, 512, 4096, 512, sVK, sQKV, sQKV, 1.f, pz, NPIX);

    // 7) RMSNorm + gate (in place on g_attn)
    rmsgate_kernel<<<dim3(16, BATCH), 256>>>(attn_norm_w);

    // 8) ypre = proj_w @ o   (NN, M=512, N=4096, K=512), A shared
    gemm_tile<false, false><<<dim3(32, 4, BATCH), 256>>>(
        proj_w, pattn, pypre, 512, 4096, 512, 0, sQKV, sQKV, 1.f, nullptr, 0);

    // 9) BN2 stats
    bn_stats_kernel<<<512, 256>>>(pypre, proj_gamma, proj_beta, pa2, pb2, 512);

    // 10) apply BN2 -> out
    bnapply_kernel<<<16384, 256>>>(out);
}

// round 2
// speedup vs baseline: 1.0843x; 1.0843x over previous
#include <cuda_runtime.h>
#include <math.h>

// ---------------------------------------------------------------------------
// SHMA (single-head linear attention) block, fp32, FFMA2-packed GEMMs.
// B=8, dim=d=512, N=64*64=4096, qkvg channels = 2048.
// ---------------------------------------------------------------------------

#define BATCH 8
#define DIM   512
#define NPIX  4096
#define C4    2048

typedef unsigned long long u64;

// Scratch (static device globals; allocation inside kernel_launch is forbidden)
__device__ float g_y[67108864];     // (8, 2048, 4096)  y = qkvg_w @ x
__device__ float g_q[16777216];     // (8, 512, 4096)
__device__ float g_k[16777216];
__device__ float g_v[16777216];
__device__ float g_attn[16777216];  // attn, then o (in place)
__device__ float g_ypre[16777216];  // proj output pre-BN
__device__ float g_vk[2097152];     // (8, 512, 512)
__device__ float g_vkp[8388608];    // (8*4 partials, 512, 512) split-K partials
__device__ float g_a1[2048];        // BN1 affine scale
__device__ float g_b1[2048];        // BN1 affine bias
__device__ float g_a2[512];
__device__ float g_b2[512];
__device__ float g_kmean[4096];     // (8, 512)
__device__ float g_z[32768];        // (8, 4096)

__device__ __forceinline__ u64 pack2(float x, float y)
{
    u64 r;
    asm("mov.b64 %0, {%1, %2};" : "=l"(r) : "f"(x), "f"(y));
    return r;
}
__device__ __forceinline__ void fma2(u64& d, u64 a, u64 b)
{
    asm("fma.rn.f32x2 %0, %1, %2, %3;" : "=l"(d) : "l"(a), "l"(b), "l"(d));
}

// ---------------------------------------------------------------------------
// Tiled SIMT GEMM with packed f32x2 FMA.
// C[zi] = alpha * A @ B  (B optionally stored [N,K] = NT). Split-K capable:
// blockIdx.z = b * kchunks + ks; each chunk covers K elements starting at
// ks*K within a row of leading stride ldk. C is offset by zi * sC.
// 128x128 tile, K-step 16, 256 threads, 8x8 microtile per thread.
// ---------------------------------------------------------------------------
template <bool TRANSB, bool ZDIV>
__global__ void __launch_bounds__(256)
gemm_tile(const float* __restrict__ A, const float* __restrict__ B,
          float* __restrict__ C, int M, int N, int K, int ldk, int kchunks,
          long long sA, long long sB, long long sC,
          float alpha, const float* __restrict__ zbase, int zstride)
{
    const int zi = blockIdx.z;
    const int b  = zi / kchunks;
    const int ks = zi - b * kchunks;
    const long long koff = (long long)ks * K;
    A += (long long)b * sA + koff;                       // A rows stride ldk
    B += (long long)b * sB + (TRANSB ? koff : koff * N); // B rows stride ldk or N
    C += (long long)zi * sC;

    __shared__ float As[16][132];
    __shared__ float Bs[16][132];

    const int tid = threadIdx.x;
    const int m0 = blockIdx.y * 128;
    const int n0 = blockIdx.x * 128;
    const int tx = tid & 15;   // 0..15 -> n microtile
    const int ty = tid >> 4;   // 0..15 -> m microtile

    u64 acc2[8][4];
#pragma unroll
    for (int i = 0; i < 8; i++)
#pragma unroll
        for (int j = 0; j < 4; j++) acc2[i][j] = 0ULL;

    const int lr = tid >> 2;         // 0..63 (row within tile)
    const int lk = (tid & 3) * 4;    // 0,4,8,12 (k within step)
    const int bk = tid >> 5;         // 0..7
    const int bn = (tid & 31) * 4;   // 0..124

    for (int k0 = 0; k0 < K; k0 += 16) {
        // Load A tile (transpose into As[k][m])
#pragma unroll
        for (int r = 0; r < 2; r++) {
            int row = lr + r * 64;
            float4 va = *reinterpret_cast<const float4*>(
                &A[(long long)(m0 + row) * ldk + k0 + lk]);
            As[lk + 0][row] = va.x; As[lk + 1][row] = va.y;
            As[lk + 2][row] = va.z; As[lk + 3][row] = va.w;
        }
        if (TRANSB) {
            // B stored [N, K] row-major: Bs[k][n] = B[n][k]
#pragma unroll
            for (int r = 0; r < 2; r++) {
                int row = lr + r * 64;
                float4 vb = *reinterpret_cast<const float4*>(
                    &B[(long long)(n0 + row) * ldk + k0 + lk]);
                Bs[lk + 0][row] = vb.x; Bs[lk + 1][row] = vb.y;
                Bs[lk + 2][row] = vb.z; Bs[lk + 3][row] = vb.w;
            }
        } else {
            // B stored [K, N] row-major
#pragma unroll
            for (int r = 0; r < 2; r++) {
                int kk = bk + r * 8;
                float4 vb = *reinterpret_cast<const float4*>(
                    &B[(long long)(k0 + kk) * N + n0 + bn]);
                *reinterpret_cast<float4*>(&Bs[kk][bn]) = vb;
            }
        }
        __syncthreads();

#pragma unroll
        for (int kk = 0; kk < 16; kk++) {
            float a[8];
            u64 b2[4];
            *reinterpret_cast<float4*>(&a[0]) =
                *reinterpret_cast<const float4*>(&As[kk][ty * 8]);
            *reinterpret_cast<float4*>(&a[4]) =
                *reinterpret_cast<const float4*>(&As[kk][ty * 8 + 4]);
            // b pairs: adjacent n pairs map directly onto f32x2 lanes
            *reinterpret_cast<float4*>(&b2[0]) =
                *reinterpret_cast<const float4*>(&Bs[kk][tx * 8]);
            *reinterpret_cast<float4*>(&b2[2]) =
                *reinterpret_cast<const float4*>(&Bs[kk][tx * 8 + 4]);
#pragma unroll
            for (int i = 0; i < 8; i++) {
                u64 ap = pack2(a[i], a[i]);
#pragma unroll
                for (int j = 0; j < 4; j++) fma2(acc2[i][j], ap, b2[j]);
            }
        }
        __syncthreads();
    }

    float zinv[8];
    if (ZDIV) {
        const float* zp = zbase + (long long)b * zstride + n0 + tx * 8;
#pragma unroll
        for (int j = 0; j < 8; j++) zinv[j] = 1.f / zp[j];
    }

#pragma unroll
    for (int i = 0; i < 8; i++) {
        long long off = (long long)(m0 + ty * 8 + i) * N + n0 + tx * 8;
        float v[8];
#pragma unroll
        for (int j = 0; j < 4; j++) {
            float2 p = *reinterpret_cast<float2*>(&acc2[i][j]);
            v[2 * j]     = p.x * alpha;
            v[2 * j + 1] = p.y * alpha;
        }
        if (ZDIV) {
#pragma unroll
            for (int j = 0; j < 8; j++) v[j] *= zinv[j];
        }
        float4 o0, o1;
        o0.x = v[0]; o0.y = v[1]; o0.z = v[2]; o0.w = v[3];
        o1.x = v[4]; o1.y = v[5]; o1.z = v[6]; o1.w = v[7];
        *reinterpret_cast<float4*>(&C[off])     = o0;
        *reinterpret_cast<float4*>(&C[off + 4]) = o1;
    }
}

// ---------------------------------------------------------------------------
// Reduce 4 split-K partials: g_vk[b] = sum_ks g_vkp[b*4+ks]
// ---------------------------------------------------------------------------
__global__ void vk_reduce_kernel()
{
    long long i4 = (long long)(blockIdx.x * blockDim.x + threadIdx.x) * 4;
    int b = (int)(i4 >> 18);                 // 262144 elems per batch slice
    long long off = i4 & 262143;
    const float* p = g_vkp + ((long long)b * 4) * 262144 + off;
    float4 s0 = *reinterpret_cast<const float4*>(p);
    float4 s1 = *reinterpret_cast<const float4*>(p + 262144);
    float4 s2 = *reinterpret_cast<const float4*>(p + 2 * 262144);
    float4 s3 = *reinterpret_cast<const float4*>(p + 3 * 262144);
    float4 o;
    o.x = (s0.x + s1.x) + (s2.x + s3.x);
    o.y = (s0.y + s1.y) + (s2.y + s3.y);
    o.z = (s0.z + s1.z) + (s2.z + s3.z);
    o.w = (s0.w + s1.w) + (s2.w + s3.w);
    *reinterpret_cast<float4*>(g_vk + i4) = o;
}

// ---------------------------------------------------------------------------
// Block reduction (two sums)
// ---------------------------------------------------------------------------
__device__ __forceinline__ void blockReduce2(float& s1, float& s2)
{
    __shared__ float sh1[32], sh2[32];
    int lane = threadIdx.x & 31, w = threadIdx.x >> 5;
#pragma unroll
    for (int o = 16; o > 0; o >>= 1) {
        s1 += __shfl_down_sync(0xffffffffu, s1, o);
        s2 += __shfl_down_sync(0xffffffffu, s2, o);
    }
    if (lane == 0) { sh1[w] = s1; sh2[w] = s2; }
    __syncthreads();
    int nw = blockDim.x >> 5;
    if (w == 0) {
        s1 = lane < nw ? sh1[lane] : 0.f;
        s2 = lane < nw ? sh2[lane] : 0.f;
#pragma unroll
        for (int o = 16; o > 0; o >>= 1) {
            s1 += __shfl_down_sync(0xffffffffu, s1, o);
            s2 += __shfl_down_sync(0xffffffffu, s2, o);
        }
    }
}

// ---------------------------------------------------------------------------
// BatchNorm stats -> per-channel affine (a, b): out = a*y + b
// ---------------------------------------------------------------------------
__global__ void bn_stats_kernel(const float* __restrict__ y,
                                const float* __restrict__ gamma,
                                const float* __restrict__ beta,
                                float* __restrict__ a, float* __restrict__ bb,
                                int Cdim)
{
    int c = blockIdx.x;
    float s1 = 0.f, s2 = 0.f;
    for (int i = threadIdx.x; i < BATCH * NPIX; i += blockDim.x) {
        int bi = i >> 12, n = i & 4095;
        float v = y[((long long)bi * Cdim + c) * NPIX + n];
        s1 += v; s2 += v * v;
    }
    blockReduce2(s1, s2);
    if (threadIdx.x == 0) {
        const float inv = 1.f / (BATCH * NPIX);
        float mean = s1 * inv;
        float var = s2 * inv - mean * mean;
        float av = gamma[c] * rsqrtf(var + 1e-5f);
        a[c] = av;
        bb[c] = beta[c] - mean * av;
    }
}

// ---------------------------------------------------------------------------
// Materialize q (sigmoid), k (sigmoid), v (affine) from y + BN1 affine.
// Also reduce kmean[b,d]. One block per (b,d) row.
// ---------------------------------------------------------------------------
__global__ void qkv_kernel()
{
    int row = blockIdx.x;            // 0..4095
    int b = row >> 9, d = row & 511;
    long long base = ((long long)b * C4 + d) * NPIX;
    const float* yq = g_y + base;
    const float* yk = yq + (long long)DIM * NPIX;
    const float* yv = yq + 2LL * DIM * NPIX;
    long long ob = ((long long)b * DIM + d) * NPIX;
    float aq = g_a1[d],        bq = g_b1[d];
    float ak = g_a1[d + 512],  bk = g_b1[d + 512];
    float av = g_a1[d + 1024], bv = g_b1[d + 1024];
    float ks = 0.f, dummy = 0.f;
    for (int n = threadIdx.x; n < NPIX; n += blockDim.x) {
        float qv = 1.f / (1.f + expf(-(aq * yq[n] + bq)));
        float kv = 1.f / (1.f + expf(-(ak * yk[n] + bk)));
        float vv = av * yv[n] + bv;
        g_q[ob + n] = qv;
        g_k[ob + n] = kv;
        g_v[ob + n] = vv;
        ks += kv;
    }
    blockReduce2(ks, dummy);
    if (threadIdx.x == 0) g_kmean[row] = ks * (1.f / NPIX);
}

// ---------------------------------------------------------------------------
// z[b,n] = sum_d kmean[b,d]*q[b,d,n] + eps
// ---------------------------------------------------------------------------
__global__ void z_kernel()
{
    __shared__ float skm[512];
    int b = blockIdx.y;
    int n = blockIdx.x * blockDim.x + threadIdx.x;
    for (int i = threadIdx.x; i < 512; i += blockDim.x)
        skm[i] = g_kmean[b * 512 + i];
    __syncthreads();
    const float* qb = g_q + (long long)b * DIM * NPIX + n;
    float acc = 0.f;
#pragma unroll 16
    for (int d = 0; d < 512; d++) acc += skm[d] * qb[(long long)d * NPIX];
    g_z[b * NPIX + n] = acc + 5e-4f;
}

// ---------------------------------------------------------------------------
// RMSNorm over d + attn_norm_w + SiLU(gate) ; in-place on g_attn.
// ---------------------------------------------------------------------------
__global__ void rmsgate_kernel(const float* __restrict__ anw)
{
    __shared__ float sa[512], sb[512], sw[512];
    int b = blockIdx.y;
    int n = blockIdx.x * blockDim.x + threadIdx.x;
    for (int i = threadIdx.x; i < 512; i += blockDim.x) {
        sa[i] = g_a1[1536 + i];
        sb[i] = g_b1[1536 + i];
        sw[i] = anw[i];
    }
    __syncthreads();
    float* ab = g_attn + (long long)b * DIM * NPIX + n;
    const float* yg = g_y + ((long long)b * C4 + 1536) * NPIX + n;
    float ss = 0.f;
#pragma unroll 16
    for (int d = 0; d < 512; d++) {
        float t = ab[(long long)d * NPIX];
        ss += t * t;
    }
    float r = rsqrtf(ss * (1.f / 512.f) + 1e-6f);
#pragma unroll 8
    for (int d = 0; d < 512; d++) {
        float t = ab[(long long)d * NPIX];
        float gv = sa[d] * yg[(long long)d * NPIX] + sb[d];
        float sg = gv / (1.f + expf(-gv));   // silu
        ab[(long long)d * NPIX] = t * r * sw[d] * sg;
    }
}

// ---------------------------------------------------------------------------
// Apply BN2 affine -> d_out (float4 vectorized)
// ---------------------------------------------------------------------------
__global__ void bnapply_kernel(float* __restrict__ out)
{
    long long i = (long long)(blockIdx.x * blockDim.x + threadIdx.x) * 4;
    int c = (int)((i >> 12) & 511);
    float a = g_a2[c], bb = g_b2[c];
    float4 v = *reinterpret_cast<const float4*>(g_ypre + i);
    v.x = a * v.x + bb; v.y = a * v.y + bb;
    v.z = a * v.z + bb; v.w = a * v.w + bb;
    *reinterpret_cast<float4*>(out + i) = v;
}

// ---------------------------------------------------------------------------
extern "C" void kernel_launch(void* const* d_in, const int* in_sizes, int n_in,
                              void* d_out, int out_size)
{
    const float* x          = (const float*)d_in[0];
    const float* qkvg_w     = (const float*)d_in[1];
    const float* qkvg_gamma = (const float*)d_in[2];
    const float* qkvg_beta  = (const float*)d_in[3];
    const float* attn_norm_w= (const float*)d_in[4];
    const float* proj_w     = (const float*)d_in[5];
    const float* proj_gamma = (const float*)d_in[6];
    const float* proj_beta  = (const float*)d_in[7];
    float* out = (float*)d_out;

    float *py, *pq, *pk, *pv, *pattn, *pypre, *pvk, *pvkp;
    float *pa1, *pb1, *pa2, *pb2, *pz;
    cudaGetSymbolAddress((void**)&py,    g_y);
    cudaGetSymbolAddress((void**)&pq,    g_q);
    cudaGetSymbolAddress((void**)&pk,    g_k);
    cudaGetSymbolAddress((void**)&pv,    g_v);
    cudaGetSymbolAddress((void**)&pattn, g_attn);
    cudaGetSymbolAddress((void**)&pypre, g_ypre);
    cudaGetSymbolAddress((void**)&pvk,   g_vk);
    cudaGetSymbolAddress((void**)&pvkp,  g_vkp);
    cudaGetSymbolAddress((void**)&pa1,   g_a1);
    cudaGetSymbolAddress((void**)&pb1,   g_b1);
    cudaGetSymbolAddress((void**)&pa2,   g_a2);
    cudaGetSymbolAddress((void**)&pb2,   g_b2);
    cudaGetSymbolAddress((void**)&pz,    g_z);

    const long long sQKV = (long long)DIM * NPIX;       // 2097152
    const long long sY   = (long long)C4 * NPIX;        // 8388608
    const long long sVK  = (long long)DIM * DIM;        // 262144

    // 1) y = qkvg_w @ x    (M=2048, N=4096, K=512), A shared across batches
    gemm_tile<false, false><<<dim3(32, 16, BATCH), 256>>>(
        qkvg_w, x, py, 2048, 4096, 512, 512, 1, 0, sQKV, sY, 1.f, nullptr, 0);

    // 2) BN1 stats -> affine
    bn_stats_kernel<<<2048, 256>>>(py, qkvg_gamma, qkvg_beta, pa1, pb1, 2048);

    // 3) q,k,v materialization + kmean
    qkv_kernel<<<4096, 256>>>();

    // 4) z
    z_kernel<<<dim3(16, BATCH), 256>>>();

    // 5) vk = (v*s) @ (k*s)^T, split-K x4 into partials
    //    (NT, M=N=512, Kc=1024, ldk=4096), alpha = 1/4096
    gemm_tile<true, false><<<dim3(4, 4, BATCH * 4), 256>>>(
        pv, pk, pvkp, 512, 512, 1024, 4096, 4, sQKV, sQKV, sVK,
        1.f / 4096.f, nullptr, 0);
    vk_reduce_kernel<<<2048, 256>>>();

    // 6) attn = vk @ q / z   (NN, M=512, N=4096, K=512), z-divide fused
    gemm_tile<false, true><<<dim3(32, 4, BATCH), 256>>>(
        pvk, pq, pattn, 512, 4096, 512, 512, 1, sVK, sQKV, sQKV,
        1.f, pz, NPIX);

    // 7) RMSNorm + gate (in place on g_attn)
    rmsgate_kernel<<<dim3(16, BATCH), 256>>>(attn_norm_w);

    // 8) ypre = proj_w @ o   (NN, M=512, N=4096, K=512), A shared
    gemm_tile<false, false><<<dim3(32, 4, BATCH), 256>>>(
        proj_w, pattn, pypre, 512, 4096, 512, 512, 1, 0, sQKV, sQKV,
        1.f, nullptr, 0);

    // 9) BN2 stats
    bn_stats_kernel<<<512, 256>>>(pypre, proj_gamma, proj_beta, pa2, pb2, 512);

    // 10) apply BN2 -> out
    bnapply_kernel<<<16384, 256>>>(out);
}

// round 4
// speedup vs baseline: 1.4779x; 1.3630x over previous
#include <cuda_runtime.h>
#include <cuda_bf16.h>
#include <math.h>
#include <stdint.h>

// ---------------------------------------------------------------------------
// SHMA block: GEMMs via warp-level mma.sync bf16 (m16n8k16, fp32 accum),
// 3-term hi/lo split for ~1e-5 accuracy. B=8, dim=d=512, N=4096, qkvg=2048.
// ---------------------------------------------------------------------------

#define BATCH 8
#define DIM   512
#define NPIX  4096
#define C4    2048

// ---------------- scratch (static device globals) --------------------------
__device__ float g_y[67108864];                      // (8,2048,4096) f32
__device__ float g_q[16777216];                      // (8,512,4096) f32
__device__ float g_attn[16777216];                   // (8,512,4096) f32
__device__ float g_ypre[16777216];                   // (8,512,4096) f32
__device__ __nv_bfloat16 g_khi[16777216], g_klo[16777216];   // k [b][d][n]
__device__ __nv_bfloat16 g_vhi[16777216], g_vlo[16777216];   // v [b][d][n]
__device__ __nv_bfloat16 g_qthi[16777216], g_qtlo[16777216]; // q^T [b][n][d]
__device__ __nv_bfloat16 g_xthi[16777216], g_xtlo[16777216]; // x^T [b][n][c]
__device__ __nv_bfloat16 g_othi[16777216], g_otlo[16777216]; // o^T [b][n][d]
__device__ __nv_bfloat16 g_vkhi[2097152], g_vklo[2097152];   // vk [b][d][e]
__device__ __nv_bfloat16 g_wqhi[1048576], g_wqlo[1048576];   // qkvg_w
__device__ __nv_bfloat16 g_pwhi[262144],  g_pwlo[262144];    // proj_w
__device__ float g_a1[2048], g_b1[2048], g_a2[512], g_b2[512];
__device__ float g_kmean[4096], g_z[32768];

// ---------------- helpers ---------------------------------------------------
__device__ __forceinline__ uint32_t smem_u32(const void* p) {
    uint32_t a;
    asm("{ .reg .u64 t; cvta.to.shared.u64 t, %1; cvt.u32.u64 %0, t; }"
        : "=r"(a) : "l"(p));
    return a;
}
__device__ __forceinline__ void ldsm_x4(uint32_t& r0, uint32_t& r1,
                                        uint32_t& r2, uint32_t& r3,
                                        uint32_t addr) {
    asm volatile("ldmatrix.sync.aligned.m8n8.x4.shared.b16 {%0,%1,%2,%3}, [%4];"
                 : "=r"(r0), "=r"(r1), "=r"(r2), "=r"(r3) : "r"(addr));
}
__device__ __forceinline__ void mma16816(float* c, const uint32_t* a,
                                         uint32_t b0, uint32_t b1) {
    asm volatile(
        "mma.sync.aligned.m16n8k16.row.col.f32.bf16.bf16.f32 "
        "{%0,%1,%2,%3}, {%4,%5,%6,%7}, {%8,%9}, {%0,%1,%2,%3};"
        : "+f"(c[0]), "+f"(c[1]), "+f"(c[2]), "+f"(c[3])
        : "r"(a[0]), "r"(a[1]), "r"(a[2]), "r"(a[3]), "r"(b0), "r"(b1));
}

// ---------------------------------------------------------------------------
// mma.sync GEMM: C = alpha * A @ B^T
//   A [M][K] hi/lo bf16, B [N][K] hi/lo bf16 (both K-major, row stride K).
//   3 K-segments: (Ah,Bh), (Ah,Bl), (Al,Bh) accumulated in fp32.
//   128x128 tile, BK=32, 256 threads (8 warps: 4m x 2n, warp tile 32x64).
//   ZDIV: fused 1/z per output column. OUTSPLIT: write hi/lo bf16.
// ---------------------------------------------------------------------------
#define SROW 40   // padded smem row stride (bf16 elems); 80B = conflict-free ldmatrix

template <bool ZDIV, bool OUTSPLIT>
__global__ void __launch_bounds__(256)
gemm_mma(const __nv_bfloat16* __restrict__ Ahi_, const __nv_bfloat16* __restrict__ Alo_,
         const __nv_bfloat16* __restrict__ Bhi_, const __nv_bfloat16* __restrict__ Blo_,
         float* __restrict__ C_, __nv_bfloat16* __restrict__ Chi_,
         __nv_bfloat16* __restrict__ Clo_,
         int N, int K, long long sA, long long sB, long long sC,
         float alpha, const float* __restrict__ zb)
{
    __shared__ __nv_bfloat16 As[2][128 * SROW];
    __shared__ __nv_bfloat16 Bs[2][128 * SROW];
    __shared__ float zsm[128];

    const int b = blockIdx.z;
    const __nv_bfloat16* Ah = Ahi_ + (long long)b * sA;
    const __nv_bfloat16* Al = Alo_ + (long long)b * sA;
    const __nv_bfloat16* Bh = Bhi_ + (long long)b * sB;
    const __nv_bfloat16* Bl = Blo_ + (long long)b * sB;
    const int m0 = blockIdx.y << 7, n0 = blockIdx.x << 7;
    const int tid = threadIdx.x, wid = tid >> 5, lane = tid & 31;
    const int wm = wid & 3, wn = wid >> 2;          // warp tile origin
    const int tig = lane & 3, grp = lane >> 2;      // mma thread/group ids

    if (ZDIV && tid < 128)
        zsm[tid] = 1.f / zb[(long long)b * NPIX + n0 + tid];

    const int K32 = K >> 5;
    const int CH = 3 * K32;

    // load-thread mapping: slot = tid + i*256; row = slot>>2, u = slot&3
    const int lrow = tid >> 2, lu = tid & 3;

    float acc[2][8][4];
#pragma unroll
    for (int i = 0; i < 2; i++)
#pragma unroll
        for (int j = 0; j < 8; j++)
#pragma unroll
            for (int t = 0; t < 4; t++) acc[i][j][t] = 0.f;

    // gmem -> regs for chunk c
    uint4 stA[2], stB[2];
    auto fetch = [&](int c) {
        int s = c / K32;
        int kc = c - s * K32;
        const __nv_bfloat16* Ap = (s == 2) ? Al : Ah;
        const __nv_bfloat16* Bp = (s == 1) ? Bl : Bh;
        long long kp = (long long)kc << 5;
#pragma unroll
        for (int i = 0; i < 2; i++) {
            int row = lrow + (i << 6);
            stA[i] = *(const uint4*)(Ap + (long long)(m0 + row) * K + kp + (lu << 3));
            stB[i] = *(const uint4*)(Bp + (long long)(n0 + row) * K + kp + (lu << 3));
        }
    };
    auto store = [&](int bi) {
#pragma unroll
        for (int i = 0; i < 2; i++) {
            int row = lrow + (i << 6);
            *(uint4*)(&As[bi][row * SROW + (lu << 3)]) = stA[i];
            *(uint4*)(&Bs[bi][row * SROW + (lu << 3)]) = stB[i];
        }
    };

    fetch(0);
    store(0);
    __syncthreads();

    const uint32_t asb = smem_u32(&As[0][0]);
    const uint32_t bsb = smem_u32(&Bs[0][0]);
    const uint32_t lrow16 = lane & 15;            // ldmatrix row-in-16
    const uint32_t lcol8 = (lane >> 4) << 3;      // ldmatrix col-half

    for (int c = 0; c < CH; c++) {
        int cur = c & 1;
        if (c + 1 < CH) fetch(c + 1);

        uint32_t abase = asb + (uint32_t)(cur * 128 * SROW * 2);
        uint32_t bbase = bsb + (uint32_t)(cur * 128 * SROW * 2);
#pragma unroll
        for (int ko2 = 0; ko2 < 2; ko2++) {
            const uint32_t ko = ko2 << 4;
            uint32_t a[2][4];
#pragma unroll
            for (int mi = 0; mi < 2; mi++) {
                uint32_t ad = abase +
                    (((wm << 5) + (mi << 4) + lrow16) * SROW + ko + lcol8) * 2;
                ldsm_x4(a[mi][0], a[mi][1], a[mi][2], a[mi][3], ad);
            }
            uint32_t bf[4][4];
#pragma unroll
            for (int nb = 0; nb < 4; nb++) {
                uint32_t bd = bbase +
                    (((wn << 6) + (nb << 4) + lrow16) * SROW + ko + lcol8) * 2;
                ldsm_x4(bf[nb][0], bf[nb][1], bf[nb][2], bf[nb][3], bd);
            }
#pragma unroll
            for (int mi = 0; mi < 2; mi++)
#pragma unroll
                for (int ni = 0; ni < 8; ni++) {
                    int nb = ni >> 1, hf = ni & 1;
                    mma16816(acc[mi][ni], a[mi], bf[nb][hf], bf[nb][hf + 2]);
                }
        }
        __syncthreads();
        if (c + 1 < CH) {
            store(cur ^ 1);
            __syncthreads();
        }
    }

    // epilogue
    float* C = C_ + (long long)b * sC;
    __nv_bfloat16* Chi = Chi_ + (long long)b * sC;
    __nv_bfloat16* Clo = Clo_ + (long long)b * sC;
#pragma unroll
    for (int mi = 0; mi < 2; mi++) {
        int row = m0 + (wm << 5) + (mi << 4) + grp;
#pragma unroll
        for (int ni = 0; ni < 8; ni++) {
            int cl = (wn << 6) + (ni << 3) + (tig << 1);  // local col 0..127
            int col = n0 + cl;
            float v0 = acc[mi][ni][0] * alpha;
            float v1 = acc[mi][ni][1] * alpha;
            float v2 = acc[mi][ni][2] * alpha;
            float v3 = acc[mi][ni][3] * alpha;
            if (ZDIV) {
                v0 *= zsm[cl]; v1 *= zsm[cl + 1];
                v2 *= zsm[cl]; v3 *= zsm[cl + 1];
            }
            if (OUTSPLIT) {
                __nv_bfloat16 h0 = __float2bfloat16(v0);
                __nv_bfloat16 h1 = __float2bfloat16(v1);
                __nv_bfloat16 h2 = __float2bfloat16(v2);
                __nv_bfloat16 h3 = __float2bfloat16(v3);
                *(__nv_bfloat162*)(Chi + (long long)row * N + col) =
                    __halves2bfloat162(h0, h1);
                *(__nv_bfloat162*)(Chi + (long long)(row + 8) * N + col) =
                    __halves2bfloat162(h2, h3);
                *(__nv_bfloat162*)(Clo + (long long)row * N + col) =
                    __halves2bfloat162(__float2bfloat16(v0 - __bfloat162float(h0)),
                                       __float2bfloat16(v1 - __bfloat162float(h1)));
                *(__nv_bfloat162*)(Clo + (long long)(row + 8) * N + col) =
                    __halves2bfloat162(__float2bfloat16(v2 - __bfloat162float(h2)),
                                       __float2bfloat16(v3 - __bfloat162float(h3)));
            } else {
                float2 p0; p0.x = v0; p0.y = v1;
                float2 p1; p1.x = v2; p1.y = v3;
                *(float2*)(C + (long long)row * N + col) = p0;
                *(float2*)(C + (long long)(row + 8) * N + col) = p1;
            }
        }
    }
}

// ---------------------------------------------------------------------------
// elementwise / reduction kernels
// ---------------------------------------------------------------------------
__device__ __forceinline__ void blockReduce2(float& s1, float& s2)
{
    __shared__ float sh1[32], sh2[32];
    int lane = threadIdx.x & 31, w = threadIdx.x >> 5;
#pragma unroll
    for (int o = 16; o > 0; o >>= 1) {
        s1 += __shfl_down_sync(0xffffffffu, s1, o);
        s2 += __shfl_down_sync(0xffffffffu, s2, o);
    }
    if (lane == 0) { sh1[w] = s1; sh2[w] = s2; }
    __syncthreads();
    int nw = blockDim.x >> 5;
    if (w == 0) {
        s1 = lane < nw ? sh1[lane] : 0.f;
        s2 = lane < nw ? sh2[lane] : 0.f;
#pragma unroll
        for (int o = 16; o > 0; o >>= 1) {
            s1 += __shfl_down_sync(0xffffffffu, s1, o);
            s2 += __shfl_down_sync(0xffffffffu, s2, o);
        }
    }
}

__global__ void bn_stats_kernel(const float* __restrict__ y,
                                const float* __restrict__ gamma,
                                const float* __restrict__ beta,
                                float* __restrict__ a, float* __restrict__ bb,
                                int Cdim)
{
    int c = blockIdx.x;
    float s1 = 0.f, s2 = 0.f;
    for (int i = threadIdx.x; i < BATCH * NPIX; i += blockDim.x) {
        int bi = i >> 12, n = i & 4095;
        float v = y[((long long)bi * Cdim + c) * NPIX + n];
        s1 += v; s2 += v * v;
    }
    blockReduce2(s1, s2);
    if (threadIdx.x == 0) {
        const float inv = 1.f / (BATCH * NPIX);
        float mean = s1 * inv;
        float var = s2 * inv - mean * mean;
        float av = gamma[c] * rsqrtf(var + 1e-5f);
        a[c] = av;
        bb[c] = beta[c] - mean * av;
    }
}

__global__ void qkv_kernel()
{
    int row = blockIdx.x;            // 0..4095
    int b = row >> 9, d = row & 511;
    long long base = ((long long)b * C4 + d) * NPIX;
    const float* yq = g_y + base;
    const float* yk = yq + (long long)DIM * NPIX;
    const float* yv = yq + 2LL * DIM * NPIX;
    long long ob = ((long long)b * DIM + d) * NPIX;
    float aq = g_a1[d],        bq = g_b1[d];
    float ak = g_a1[d + 512],  bk = g_b1[d + 512];
    float av = g_a1[d + 1024], bv = g_b1[d + 1024];
    float ks = 0.f, dm = 0.f;
    for (int n = threadIdx.x; n < NPIX; n += blockDim.x) {
        float qv = 1.f / (1.f + expf(-(aq * yq[n] + bq)));
        float kv = 1.f / (1.f + expf(-(ak * yk[n] + bk)));
        float vv = av * yv[n] + bv;
        g_q[ob + n] = qv;
        __nv_bfloat16 kh = __float2bfloat16(kv);
        g_khi[ob + n] = kh;
        g_klo[ob + n] = __float2bfloat16(kv - __bfloat162float(kh));
        __nv_bfloat16 vh = __float2bfloat16(vv);
        g_vhi[ob + n] = vh;
        g_vlo[ob + n] = __float2bfloat16(vv - __bfloat162float(vh));
        ks += kv;
    }
    blockReduce2(ks, dm);
    if (threadIdx.x == 0) g_kmean[row] = ks * (1.f / NPIX);
}

__global__ void z_kernel()
{
    __shared__ float skm[512];
    int b = blockIdx.y;
    int n = blockIdx.x * blockDim.x + threadIdx.x;
    for (int i = threadIdx.x; i < 512; i += blockDim.x)
        skm[i] = g_kmean[b * 512 + i];
    __syncthreads();
    const float* qb = g_q + (long long)b * DIM * NPIX + n;
    float acc = 0.f;
#pragma unroll 16
    for (int d = 0; d < 512; d++) acc += skm[d] * qb[(long long)d * NPIX];
    g_z[b * NPIX + n] = acc + 5e-4f;
}

__global__ void rmsgate_kernel(const float* __restrict__ anw)
{
    __shared__ float sa[512], sb[512], sw[512];
    int b = blockIdx.y;
    int n = blockIdx.x * blockDim.x + threadIdx.x;
    for (int i = threadIdx.x; i < 512; i += blockDim.x) {
        sa[i] = g_a1[1536 + i];
        sb[i] = g_b1[1536 + i];
        sw[i] = anw[i];
    }
    __syncthreads();
    float* ab = g_attn + (long long)b * DIM * NPIX + n;
    const float* yg = g_y + ((long long)b * C4 + 1536) * NPIX + n;
    float ss = 0.f;
#pragma unroll 16
    for (int d = 0; d < 512; d++) {
        float t = ab[(long long)d * NPIX];
        ss += t * t;
    }
    float r = rsqrtf(ss * (1.f / 512.f) + 1e-6f);
#pragma unroll 8
    for (int d = 0; d < 512; d++) {
        float t = ab[(long long)d * NPIX];
        float gv = sa[d] * yg[(long long)d * NPIX] + sb[d];
        float sg = gv / (1.f + expf(-gv));
        ab[(long long)d * NPIX] = t * r * sw[d] * sg;
    }
}

__global__ void bnapply_kernel(float* __restrict__ out)
{
    long long i = (long long)(blockIdx.x * blockDim.x + threadIdx.x) * 4;
    int c = (int)((i >> 12) & 511);
    float a = g_a2[c], bb = g_b2[c];
    float4 v = *reinterpret_cast<const float4*>(g_ypre + i);
    v.x = a * v.x + bb; v.y = a * v.y + bb;
    v.z = a * v.z + bb; v.w = a * v.w + bb;
    *reinterpret_cast<float4*>(out + i) = v;
}

__global__ void convert_split(const float* __restrict__ s,
                              __nv_bfloat16* __restrict__ hi,
                              __nv_bfloat16* __restrict__ lo, int n)
{
    int i = blockIdx.x * blockDim.x + threadIdx.x;
    if (i < n) {
        float v = s[i];
        __nv_bfloat16 h = __float2bfloat16(v);
        hi[i] = h;
        lo[i] = __float2bfloat16(v - __bfloat162float(h));
    }
}

// transpose + hi/lo split: src [b][R][Cc] f32 -> dst [b][Cc][R] bf16
__global__ void transpose_split(const float* __restrict__ src,
                                __nv_bfloat16* __restrict__ dhi,
                                __nv_bfloat16* __restrict__ dlo, int R, int Cc)
{
    __shared__ float t[32][33];
    int b = blockIdx.z;
    long long o = (long long)b * R * Cc;
    src += o; dhi += o; dlo += o;
    int c0 = blockIdx.x * 32, r0 = blockIdx.y * 32;
    int tx = threadIdx.x, ty = threadIdx.y;
#pragma unroll
    for (int i = 0; i < 4; i++)
        t[ty + 8 * i][tx] = src[(long long)(r0 + ty + 8 * i) * Cc + c0 + tx];
    __syncthreads();
#pragma unroll
    for (int i = 0; i < 4; i++) {
        int cc = c0 + ty + 8 * i;
        float v = t[tx][ty + 8 * i];
        __nv_bfloat16 h = __float2bfloat16(v);
        dhi[(long long)cc * R + r0 + tx] = h;
        dlo[(long long)cc * R + r0 + tx] = __float2bfloat16(v - __bfloat162float(h));
    }
}

// ---------------------------------------------------------------------------
extern "C" void kernel_launch(void* const* d_in, const int* in_sizes, int n_in,
                              void* d_out, int out_size)
{
    const float* x           = (const float*)d_in[0];
    const float* qkvg_w      = (const float*)d_in[1];
    const float* qkvg_gamma  = (const float*)d_in[2];
    const float* qkvg_beta   = (const float*)d_in[3];
    const float* attn_norm_w = (const float*)d_in[4];
    const float* proj_w      = (const float*)d_in[5];
    const float* proj_gamma  = (const float*)d_in[6];
    const float* proj_beta   = (const float*)d_in[7];
    float* out = (float*)d_out;

    float *py, *pq, *pattn, *pypre, *pa1, *pb1, *pa2, *pb2, *pz;
    __nv_bfloat16 *pkhi, *pklo, *pvhi, *pvlo, *pqthi, *pqtlo, *pxthi, *pxtlo;
    __nv_bfloat16 *pothi, *potlo, *pvkhi, *pvklo, *pwqhi, *pwqlo, *ppwhi, *ppwlo;
    cudaGetSymbolAddress((void**)&py,    g_y);
    cudaGetSymbolAddress((void**)&pq,    g_q);
    cudaGetSymbolAddress((void**)&pattn, g_attn);
    cudaGetSymbolAddress((void**)&pypre, g_ypre);
    cudaGetSymbolAddress((void**)&pa1,   g_a1);
    cudaGetSymbolAddress((void**)&pb1,   g_b1);
    cudaGetSymbolAddress((void**)&pa2,   g_a2);
    cudaGetSymbolAddress((void**)&pb2,   g_b2);
    cudaGetSymbolAddress((void**)&pz,    g_z);
    cudaGetSymbolAddress((void**)&pkhi,  g_khi);
    cudaGetSymbolAddress((void**)&pklo,  g_klo);
    cudaGetSymbolAddress((void**)&pvhi,  g_vhi);
    cudaGetSymbolAddress((void**)&pvlo,  g_vlo);
    cudaGetSymbolAddress((void**)&pqthi, g_qthi);
    cudaGetSymbolAddress((void**)&pqtlo, g_qtlo);
    cudaGetSymbolAddress((void**)&pxthi, g_xthi);
    cudaGetSymbolAddress((void**)&pxtlo, g_xtlo);
    cudaGetSymbolAddress((void**)&pothi, g_othi);
    cudaGetSymbolAddress((void**)&potlo, g_otlo);
    cudaGetSymbolAddress((void**)&pvkhi, g_vkhi);
    cudaGetSymbolAddress((void**)&pvklo, g_vklo);
    cudaGetSymbolAddress((void**)&pwqhi, g_wqhi);
    cudaGetSymbolAddress((void**)&pwqlo, g_wqlo);
    cudaGetSymbolAddress((void**)&ppwhi, g_pwhi);
    cudaGetSymbolAddress((void**)&ppwlo, g_pwlo);

    const long long sQKV = (long long)DIM * NPIX;   // 2097152
    const long long sY   = (long long)C4 * NPIX;    // 8388608
    const long long sVK  = (long long)DIM * DIM;    // 262144

    // input conversions
    convert_split<<<4096, 256>>>(qkvg_w, pwqhi, pwqlo, C4 * DIM);
    convert_split<<<1024, 256>>>(proj_w, ppwhi, ppwlo, DIM * DIM);
    transpose_split<<<dim3(128, 16, BATCH), dim3(32, 8)>>>(x, pxthi, pxtlo, DIM, NPIX);

    // 1) y = qkvg_w @ x : A [2048][512] shared, B = x^T [4096][512]
    gemm_mma<false, false><<<dim3(32, 16, BATCH), 256>>>(
        pwqhi, pwqlo, pxthi, pxtlo, py, nullptr, nullptr,
        4096, 512, 0, sQKV, sY, 1.f, nullptr);

    // 2) BN1 stats
    bn_stats_kernel<<<2048, 256>>>(py, qkvg_gamma, qkvg_beta, pa1, pb1, 2048);

    // 3) q,k,v + kmean (k,v split to bf16 here)
    qkv_kernel<<<4096, 256>>>();

    // 4) z
    z_kernel<<<dim3(16, BATCH), 256>>>();

    // 5) q^T split
    transpose_split<<<dim3(128, 16, BATCH), dim3(32, 8)>>>(pq, pqthi, pqtlo, DIM, NPIX);

    // 6) vk = (v*s)(k*s)^T : A=v [512][4096], B=k [512][4096], out split bf16
    gemm_mma<false, true><<<dim3(4, 4, BATCH), 256>>>(
        pvhi, pvlo, pkhi, pklo, nullptr, pvkhi, pvklo,
        512, 4096, sQKV, sQKV, sVK, 1.f / 4096.f, nullptr);

    // 7) attn = vk @ q / z : A=vk [512][512], B=q^T [4096][512], z fused
    gemm_mma<true, false><<<dim3(32, 4, BATCH), 256>>>(
        pvkhi, pvklo, pqthi, pqtlo, pattn, nullptr, nullptr,
        4096, 512, sVK, sQKV, sQKV, 1.f, pz);

    // 8) RMSNorm + gate (in place)
    rmsgate_kernel<<<dim3(16, BATCH), 256>>>(attn_norm_w);

    // 9) o^T split
    transpose_split<<<dim3(128, 16, BATCH), dim3(32, 8)>>>(pattn, pothi, potlo, DIM, NPIX);

    // 10) ypre = proj_w @ o : A shared [512][512], B=o^T [4096][512]
    gemm_mma<false, false><<<dim3(32, 4, BATCH), 256>>>(
        ppwhi, ppwlo, pothi, potlo, pypre, nullptr, nullptr,
        4096, 512, 0, sQKV, sQKV, 1.f, nullptr);

    // 11) BN2
    bn_stats_kernel<<<512, 256>>>(pypre, proj_gamma, proj_beta, pa2, pb2, 512);
    bnapply_kernel<<<16384, 256>>>(out);
}

// round 5
// speedup vs baseline: 1.8290x; 1.2375x over previous
#include <cuda_runtime.h>
#include <cuda_bf16.h>
#include <math.h>
#include <stdint.h>

// ---------------------------------------------------------------------------
// SHMA block: mma.sync bf16 GEMMs (3-term hi/lo split), n-major dataflow.
// B=8, dim=d=512, N=4096, qkvg=2048.
// ---------------------------------------------------------------------------

#define BATCH 8
#define DIM   512
#define NPIX  4096
#define C4    2048

// ---------------- scratch (static device globals) --------------------------
__device__ float g_y[67108864];                      // y^T (8*4096, 2048) f32
__device__ float g_attn[16777216];                   // attn^T (8*4096, 512) f32
__device__ float g_ypre[16777216];                   // ypre (8, 512, 4096) f32
__device__ __nv_bfloat16 g_khi[16777216], g_klo[16777216];   // k [b][d][n]
__device__ __nv_bfloat16 g_vhi[16777216], g_vlo[16777216];   // v [b][d][n]
__device__ __nv_bfloat16 g_qthi[16777216], g_qtlo[16777216]; // q^T [b][n][d]
__device__ __nv_bfloat16 g_xthi[16777216], g_xtlo[16777216]; // x^T [b][n][c]
__device__ __nv_bfloat16 g_othi[16777216], g_otlo[16777216]; // o^T [b][n][d]
__device__ __nv_bfloat16 g_vkhi[2097152], g_vklo[2097152];   // vk [b][d][e]
__device__ __nv_bfloat16 g_wqhi[1048576], g_wqlo[1048576];   // qkvg_w
__device__ __nv_bfloat16 g_pwhi[262144],  g_pwlo[262144];    // proj_w
__device__ float g_a1[2048], g_b1[2048], g_a2[512], g_b2[512];
__device__ float g_s1[2048], g_s2[2048];
__device__ float g_ksum[4096], g_z[32768];

// ---------------- helpers ---------------------------------------------------
__device__ __forceinline__ uint32_t smem_u32(const void* p) {
    uint32_t a;
    asm("{ .reg .u64 t; cvta.to.shared.u64 t, %1; cvt.u32.u64 %0, t; }"
        : "=r"(a) : "l"(p));
    return a;
}
__device__ __forceinline__ void ldsm_x4(uint32_t& r0, uint32_t& r1,
                                        uint32_t& r2, uint32_t& r3,
                                        uint32_t addr) {
    asm volatile("ldmatrix.sync.aligned.m8n8.x4.shared.b16 {%0,%1,%2,%3}, [%4];"
                 : "=r"(r0), "=r"(r1), "=r"(r2), "=r"(r3) : "r"(addr));
}
__device__ __forceinline__ void mma16816(float* c, const uint32_t* a,
                                         uint32_t b0, uint32_t b1) {
    asm volatile(
        "mma.sync.aligned.m16n8k16.row.col.f32.bf16.bf16.f32 "
        "{%0,%1,%2,%3}, {%4,%5,%6,%7}, {%8,%9}, {%0,%1,%2,%3};"
        : "+f"(c[0]), "+f"(c[1]), "+f"(c[2]), "+f"(c[3])
        : "r"(a[0]), "r"(a[1]), "r"(a[2]), "r"(a[3]), "r"(b0), "r"(b1));
}
__device__ __forceinline__ void cpasync16(uint32_t dst, const void* src) {
    asm volatile("cp.async.cg.shared.global [%0], [%1], 16;"
                 :: "r"(dst), "l"(src));
}
#define CP_COMMIT() asm volatile("cp.async.commit_group;" ::: "memory")
#define CP_WAIT(n)  asm volatile("cp.async.wait_group %0;" :: "n"(n) : "memory")

// ---------------------------------------------------------------------------
// mma.sync GEMM: C = alpha * A @ B^T
//   A [M][K] hi/lo bf16, B [N][K] hi/lo bf16 (K-major, ld=K).
//   3 K-segments: (Ah,Bh), (Ah,Bl), (Al,Bh) in fp32 accum.
//   128x128 CTA tile, BK=32, 128 threads (4 warps 2x2, warp tile 64x64),
//   cp.async double-buffered.  ZDIV: divide output ROW r by z[b*4096+r].
//   OUTSPLIT: write hi/lo bf16.
// ---------------------------------------------------------------------------
#define SROW 40            // padded smem row stride (bf16); 80B, 16B-aligned
#define BUFB (128 * SROW * 2)   // bytes per operand buffer

template <bool ZDIV, bool OUTSPLIT>
__global__ void __launch_bounds__(128)
gemm_mma(const __nv_bfloat16* __restrict__ Ahi_, const __nv_bfloat16* __restrict__ Alo_,
         const __nv_bfloat16* __restrict__ Bhi_, const __nv_bfloat16* __restrict__ Blo_,
         float* __restrict__ C_, __nv_bfloat16* __restrict__ Chi_,
         __nv_bfloat16* __restrict__ Clo_,
         int N, int K, long long sA, long long sB, long long sC,
         float alpha, const float* __restrict__ zb)
{
    __shared__ __nv_bfloat16 As[2][128 * SROW];
    __shared__ __nv_bfloat16 Bs[2][128 * SROW];
    __shared__ float zsm[128];

    const int b = blockIdx.z;
    const __nv_bfloat16* Ah = Ahi_ + (long long)b * sA;
    const __nv_bfloat16* Al = Alo_ + (long long)b * sA;
    const __nv_bfloat16* Bh = Bhi_ + (long long)b * sB;
    const __nv_bfloat16* Bl = Blo_ + (long long)b * sB;
    const int m0 = blockIdx.y << 7, n0 = blockIdx.x << 7;
    const int tid = threadIdx.x, wid = tid >> 5, lane = tid & 31;
    const int wm = wid & 1, wn = wid >> 1;          // 2x2 warp grid
    const int tig = lane & 3, grp = lane >> 2;

    if (ZDIV) zsm[tid] = 1.f / zb[(long long)b * 4096 + m0 + tid];

    const int K32 = K >> 5;
    const int CH = 3 * K32;

    const uint32_t asb = smem_u32(&As[0][0]);
    const uint32_t bsb = smem_u32(&Bs[0][0]);

    float acc[4][8][4];
#pragma unroll
    for (int i = 0; i < 4; i++)
#pragma unroll
        for (int j = 0; j < 8; j++)
#pragma unroll
            for (int t = 0; t < 4; t++) acc[i][j][t] = 0.f;

    // cp.async loader: 8 x 16B per thread per chunk (4 for A, 4 for B)
    auto load = [&](int c, int bi) {
        int s = c / K32;
        int kc = c - s * K32;
        const __nv_bfloat16* Ap = (s == 2) ? Al : Ah;
        const __nv_bfloat16* Bp = (s == 1) ? Bl : Bh;
        long long kp = (long long)kc << 5;
        uint32_t ab = asb + (uint32_t)bi * BUFB;
        uint32_t bb = bsb + (uint32_t)bi * BUFB;
#pragma unroll
        for (int i = 0; i < 4; i++) {
            int slot = tid + (i << 7);
            int row = slot >> 2, u = slot & 3;
            uint32_t d = (uint32_t)(row * (SROW * 2) + (u << 4));
            cpasync16(ab + d, Ap + (long long)(m0 + row) * K + kp + (u << 3));
            cpasync16(bb + d, Bp + (long long)(n0 + row) * K + kp + (u << 3));
        }
        CP_COMMIT();
    };

    load(0, 0);

    const uint32_t lrow16 = lane & 15;
    const uint32_t lcol8 = (lane >> 4) << 3;

    for (int c = 0; c < CH; c++) {
        int cur = c & 1;
        if (c + 1 < CH) { load(c + 1, cur ^ 1); CP_WAIT(1); }
        else            { CP_WAIT(0); }
        __syncthreads();

        uint32_t abase = asb + (uint32_t)cur * BUFB;
        uint32_t bbase = bsb + (uint32_t)cur * BUFB;
#pragma unroll
        for (int ko2 = 0; ko2 < 2; ko2++) {
            const uint32_t ko = ko2 << 4;
            uint32_t a[4][4];
#pragma unroll
            for (int mi = 0; mi < 4; mi++) {
                uint32_t ad = abase +
                    (((wm << 6) + (mi << 4) + lrow16) * SROW + ko + lcol8) * 2;
                ldsm_x4(a[mi][0], a[mi][1], a[mi][2], a[mi][3], ad);
            }
            uint32_t bf[4][4];
#pragma unroll
            for (int nb = 0; nb < 4; nb++) {
                uint32_t bd = bbase +
                    (((wn << 6) + (nb << 4) + lrow16) * SROW + ko + lcol8) * 2;
                ldsm_x4(bf[nb][0], bf[nb][1], bf[nb][2], bf[nb][3], bd);
            }
#pragma unroll
            for (int mi = 0; mi < 4; mi++)
#pragma unroll
                for (int ni = 0; ni < 8; ni++) {
                    int nb = ni >> 1, hf = ni & 1;
                    mma16816(acc[mi][ni], a[mi], bf[nb][hf], bf[nb][hf + 2]);
                }
        }
        __syncthreads();
    }

    // epilogue
    float* C = C_ + (long long)b * sC;
    __nv_bfloat16* Chi = Chi_ + (long long)b * sC;
    __nv_bfloat16* Clo = Clo_ + (long long)b * sC;
#pragma unroll
    for (int mi = 0; mi < 4; mi++) {
        int rl = (wm << 6) + (mi << 4) + grp;      // local row (and rl+8)
        int row = m0 + rl;
        float zr0 = 1.f, zr1 = 1.f;
        if (ZDIV) { zr0 = zsm[rl]; zr1 = zsm[rl + 8]; }
#pragma unroll
        for (int ni = 0; ni < 8; ni++) {
            int col = n0 + (wn << 6) + (ni << 3) + (tig << 1);
            float v0 = acc[mi][ni][0] * alpha;
            float v1 = acc[mi][ni][1] * alpha;
            float v2 = acc[mi][ni][2] * alpha;
            float v3 = acc[mi][ni][3] * alpha;
            if (ZDIV) { v0 *= zr0; v1 *= zr0; v2 *= zr1; v3 *= zr1; }
            if (OUTSPLIT) {
                __nv_bfloat16 h0 = __float2bfloat16(v0);
                __nv_bfloat16 h1 = __float2bfloat16(v1);
                __nv_bfloat16 h2 = __float2bfloat16(v2);
                __nv_bfloat16 h3 = __float2bfloat16(v3);
                *(__nv_bfloat162*)(Chi + (long long)row * N + col) =
                    __halves2bfloat162(h0, h1);
                *(__nv_bfloat162*)(Chi + (long long)(row + 8) * N + col) =
                    __halves2bfloat162(h2, h3);
                *(__nv_bfloat162*)(Clo + (long long)row * N + col) =
                    __halves2bfloat162(__float2bfloat16(v0 - __bfloat162float(h0)),
                                       __float2bfloat16(v1 - __bfloat162float(h1)));
                *(__nv_bfloat162*)(Clo + (long long)(row + 8) * N + col) =
                    __halves2bfloat162(__float2bfloat16(v2 - __bfloat162float(h2)),
                                       __float2bfloat16(v3 - __bfloat162float(h3)));
            } else {
                float2 p0; p0.x = v0; p0.y = v1;
                float2 p1; p1.x = v2; p1.y = v3;
                *(float2*)(C + (long long)row * N + col) = p0;
                *(float2*)(C + (long long)(row + 8) * N + col) = p1;
            }
        }
    }
}

// ---------------------------------------------------------------------------
// elementwise / reduction kernels
// ---------------------------------------------------------------------------
__global__ void zero_kernel()
{
    int i = blockIdx.x * 256 + threadIdx.x;          // 8192 floats
    if (i < 2048) { g_s1[i] = 0.f; g_s2[i] = 0.f; }
    if (i < 4096) g_ksum[i] = 0.f;
}

// BN1 column stats over y^T [32768][2048]: partial sums via atomics
__global__ void bn1_colstats()
{
    int c = blockIdx.x * 256 + threadIdx.x;
    int r0 = blockIdx.y * 512;
    const float* p = g_y + (long long)r0 * C4 + c;
    float s1 = 0.f, s2 = 0.f;
#pragma unroll 4
    for (int r = 0; r < 512; r++) {
        float v = p[(long long)r * C4];
        s1 += v; s2 += v * v;
    }
    atomicAdd(&g_s1[c], s1);
    atomicAdd(&g_s2[c], s2);
}

__global__ void bn1_finalize(const float* __restrict__ gamma,
                             const float* __restrict__ beta)
{
    int c = blockIdx.x * 256 + threadIdx.x;
    const float inv = 1.f / (BATCH * NPIX);
    float mean = g_s1[c] * inv;
    float var = g_s2[c] * inv - mean * mean;
    float av = gamma[c] * rsqrtf(var + 1e-5f);
    g_a1[c] = av;
    g_b1[c] = beta[c] - mean * av;
}

// q: sigmoid(affine(y^T[:, 0:512])) -> q^T hi/lo bf16 [r][512]
__global__ void q_kernel()
{
    int i = blockIdx.x * 256 + threadIdx.x;   // float4 index
    int r = i >> 7;
    int dg = (i & 127) << 2;
    float4 y4 = *(const float4*)(g_y + (long long)r * C4 + dg);
    float4 a4 = *(const float4*)(g_a1 + dg);
    float4 b4 = *(const float4*)(g_b1 + dg);
    float q0 = 1.f / (1.f + expf(-(a4.x * y4.x + b4.x)));
    float q1 = 1.f / (1.f + expf(-(a4.y * y4.y + b4.y)));
    float q2 = 1.f / (1.f + expf(-(a4.z * y4.z + b4.z)));
    float q3 = 1.f / (1.f + expf(-(a4.w * y4.w + b4.w)));
    __nv_bfloat16 h0 = __float2bfloat16(q0), h1 = __float2bfloat16(q1);
    __nv_bfloat16 h2 = __float2bfloat16(q2), h3 = __float2bfloat16(q3);
    long long o = (long long)r * DIM + dg;
    *(__nv_bfloat162*)(g_qthi + o)     = __halves2bfloat162(h0, h1);
    *(__nv_bfloat162*)(g_qthi + o + 2) = __halves2bfloat162(h2, h3);
    *(__nv_bfloat162*)(g_qtlo + o) =
        __halves2bfloat162(__float2bfloat16(q0 - __bfloat162float(h0)),
                           __float2bfloat16(q1 - __bfloat162float(h1)));
    *(__nv_bfloat162*)(g_qtlo + o + 2) =
        __halves2bfloat162(__float2bfloat16(q2 - __bfloat162float(h2)),
                           __float2bfloat16(q3 - __bfloat162float(h3)));
}

// k,v: 32x32 tile transpose y^T -> [b][d][n] hi/lo, sigmoid/affine, ksum
__global__ void kvt_kernel()
{
    __shared__ float tk[32][33], tv[32][33];
    int bz = blockIdx.z;
    int n0 = blockIdx.x << 5, d0 = blockIdx.y << 5;
    int tx = threadIdx.x, ty = threadIdx.y;
    float ak = g_a1[512 + d0 + tx],  bk = g_b1[512 + d0 + tx];
    float av = g_a1[1024 + d0 + tx], bv = g_b1[1024 + d0 + tx];
    long long rowbase = ((long long)(bz << 12) + n0) * C4;
#pragma unroll
    for (int i = 0; i < 4; i++) {
        long long rr = rowbase + (long long)(ty + 8 * i) * C4;
        float kraw = g_y[rr + 512 + d0 + tx];
        float vraw = g_y[rr + 1024 + d0 + tx];
        tk[ty + 8 * i][tx] = 1.f / (1.f + expf(-(ak * kraw + bk)));
        tv[ty + 8 * i][tx] = av * vraw + bv;
    }
    __syncthreads();
#pragma unroll
    for (int i = 0; i < 4; i++) {
        int d = d0 + ty + 8 * i;
        int n = n0 + tx;
        float ks = tk[tx][ty + 8 * i];
        float vs = tv[tx][ty + 8 * i];
        long long o = ((long long)(bz << 9) + d) * NPIX + n;
        __nv_bfloat16 kh = __float2bfloat16(ks);
        g_khi[o] = kh;
        g_klo[o] = __float2bfloat16(ks - __bfloat162float(kh));
        __nv_bfloat16 vh = __float2bfloat16(vs);
        g_vhi[o] = vh;
        g_vlo[o] = __float2bfloat16(vs - __bfloat162float(vh));
        float s = ks;
#pragma unroll
        for (int off = 16; off > 0; off >>= 1)
            s += __shfl_down_sync(0xffffffffu, s, off);
        if (tx == 0) atomicAdd(&g_ksum[(bz << 9) + d], s);
    }
}

// z[r] = sum_d kmean[d] * q[r][d] + eps   (warp per row)
__global__ void z_kernel()
{
    __shared__ float km[512];
    int r0 = blockIdx.x << 3;
    int bb = r0 >> 12;
    for (int i = threadIdx.x; i < 512; i += 256)
        km[i] = g_ksum[(bb << 9) + i] * (1.f / NPIX);
    __syncthreads();
    int w = threadIdx.x >> 5, lane = threadIdx.x & 31;
    int r = r0 + w;
    const __nv_bfloat16* qh = g_qthi + (long long)r * DIM;
    const __nv_bfloat16* ql = g_qtlo + (long long)r * DIM;
    float s = 0.f;
#pragma unroll
    for (int i = 0; i < 16; i++) {
        int d = lane + (i << 5);
        s += km[d] * (__bfloat162float(qh[d]) + __bfloat162float(ql[d]));
    }
#pragma unroll
    for (int off = 16; off > 0; off >>= 1)
        s += __shfl_down_sync(0xffffffffu, s, off);
    if (lane == 0) g_z[r] = s + 5e-4f;
}

// RMSNorm row (over d) + anw + SiLU(gate) -> o^T hi/lo bf16 [r][512]
__global__ void rmsgate_kernel(const float* __restrict__ anw)
{
    __shared__ float red[4];
    int r = blockIdx.x;
    int t = threadIdx.x;               // 128 threads, 4 d's each
    int dg = t << 2;
    const float* at = g_attn + (long long)r * DIM + dg;
    float4 a = *(const float4*)at;
    float ss = a.x * a.x + a.y * a.y + a.z * a.z + a.w * a.w;
    int lane = t & 31, w = t >> 5;
#pragma unroll
    for (int off = 16; off > 0; off >>= 1)
        ss += __shfl_down_sync(0xffffffffu, ss, off);
    if (lane == 0) red[w] = ss;
    __syncthreads();
    float tot = red[0] + red[1] + red[2] + red[3];
    float rms = rsqrtf(tot * (1.f / DIM) + 1e-6f);

    float4 ga = *(const float4*)(g_a1 + 1536 + dg);
    float4 gb = *(const float4*)(g_b1 + 1536 + dg);
    float4 yg = *(const float4*)(g_y + (long long)r * C4 + 1536 + dg);
    float4 wn = *(const float4*)(anw + dg);
    float g0 = ga.x * yg.x + gb.x, g1 = ga.y * yg.y + gb.y;
    float g2 = ga.z * yg.z + gb.z, g3 = ga.w * yg.w + gb.w;
    float o0 = a.x * rms * wn.x * (g0 / (1.f + expf(-g0)));
    float o1 = a.y * rms * wn.y * (g1 / (1.f + expf(-g1)));
    float o2 = a.z * rms * wn.z * (g2 / (1.f + expf(-g2)));
    float o3 = a.w * rms * wn.w * (g3 / (1.f + expf(-g3)));
    __nv_bfloat16 h0 = __float2bfloat16(o0), h1 = __float2bfloat16(o1);
    __nv_bfloat16 h2 = __float2bfloat16(o2), h3 = __float2bfloat16(o3);
    long long o = (long long)r * DIM + dg;
    *(__nv_bfloat162*)(g_othi + o)     = __halves2bfloat162(h0, h1);
    *(__nv_bfloat162*)(g_othi + o + 2) = __halves2bfloat162(h2, h3);
    *(__nv_bfloat162*)(g_otlo + o) =
        __halves2bfloat162(__float2bfloat16(o0 - __bfloat162float(h0)),
                           __float2bfloat16(o1 - __bfloat162float(h1)));
    *(__nv_bfloat162*)(g_otlo + o + 2) =
        __halves2bfloat162(__float2bfloat16(o2 - __bfloat162float(h2)),
                           __float2bfloat16(o3 - __bfloat162float(h3)));
}

__device__ __forceinline__ void blockReduce2(float& s1, float& s2)
{
    __shared__ float sh1[32], sh2[32];
    int lane = threadIdx.x & 31, w = threadIdx.x >> 5;
#pragma unroll
    for (int o = 16; o > 0; o >>= 1) {
        s1 += __shfl_down_sync(0xffffffffu, s1, o);
        s2 += __shfl_down_sync(0xffffffffu, s2, o);
    }
    if (lane == 0) { sh1[w] = s1; sh2[w] = s2; }
    __syncthreads();
    int nw = blockDim.x >> 5;
    if (w == 0) {
        s1 = lane < nw ? sh1[lane] : 0.f;
        s2 = lane < nw ? sh2[lane] : 0.f;
#pragma unroll
        for (int o = 16; o > 0; o >>= 1) {
            s1 += __shfl_down_sync(0xffffffffu, s1, o);
            s2 += __shfl_down_sync(0xffffffffu, s2, o);
        }
    }
}

// BN2 stats over ypre [b][c][n] (c-major rows)
__global__ void bn_stats_kernel(const float* __restrict__ y,
                                const float* __restrict__ gamma,
                                const float* __restrict__ beta,
                                float* __restrict__ a, float* __restrict__ bb,
                                int Cdim)
{
    int c = blockIdx.x;
    float s1 = 0.f, s2 = 0.f;
    for (int i = threadIdx.x; i < BATCH * NPIX; i += blockDim.x) {
        int bi = i >> 12, n = i & 4095;
        float v = y[((long long)bi * Cdim + c) * NPIX + n];
        s1 += v; s2 += v * v;
    }
    blockReduce2(s1, s2);
    if (threadIdx.x == 0) {
        const float inv = 1.f / (BATCH * NPIX);
        float mean = s1 * inv;
        float var = s2 * inv - mean * mean;
        float av = gamma[c] * rsqrtf(var + 1e-5f);
        a[c] = av;
        bb[c] = beta[c] - mean * av;
    }
}

__global__ void bnapply_kernel(float* __restrict__ out)
{
    long long i = (long long)(blockIdx.x * blockDim.x + threadIdx.x) * 4;
    int c = (int)((i >> 12) & 511);
    float a = g_a2[c], bb = g_b2[c];
    float4 v = *reinterpret_cast<const float4*>(g_ypre + i);
    v.x = a * v.x + bb; v.y = a * v.y + bb;
    v.z = a * v.z + bb; v.w = a * v.w + bb;
    *reinterpret_cast<float4*>(out + i) = v;
}

__global__ void convert_split(const float* __restrict__ s,
                              __nv_bfloat16* __restrict__ hi,
                              __nv_bfloat16* __restrict__ lo, int n)
{
    int i = blockIdx.x * blockDim.x + threadIdx.x;
    if (i < n) {
        float v = s[i];
        __nv_bfloat16 h = __float2bfloat16(v);
        hi[i] = h;
        lo[i] = __float2bfloat16(v - __bfloat162float(h));
    }
}

// transpose + hi/lo split: src [b][R][Cc] f32 -> dst [b][Cc][R] bf16
__global__ void transpose_split(const float* __restrict__ src,
                                __nv_bfloat16* __restrict__ dhi,
                                __nv_bfloat16* __restrict__ dlo, int R, int Cc)
{
    __shared__ float t[32][33];
    int b = blockIdx.z;
    long long o = (long long)b * R * Cc;
    src += o; dhi += o; dlo += o;
    int c0 = blockIdx.x * 32, r0 = blockIdx.y * 32;
    int tx = threadIdx.x, ty = threadIdx.y;
#pragma unroll
    for (int i = 0; i < 4; i++)
        t[ty + 8 * i][tx] = src[(long long)(r0 + ty + 8 * i) * Cc + c0 + tx];
    __syncthreads();
#pragma unroll
    for (int i = 0; i < 4; i++) {
        int cc = c0 + ty + 8 * i;
        float v = t[tx][ty + 8 * i];
        __nv_bfloat16 h = __float2bfloat16(v);
        dhi[(long long)cc * R + r0 + tx] = h;
        dlo[(long long)cc * R + r0 + tx] = __float2bfloat16(v - __bfloat162float(h));
    }
}

// ---------------------------------------------------------------------------
extern "C" void kernel_launch(void* const* d_in, const int* in_sizes, int n_in,
                              void* d_out, int out_size)
{
    const float* x           = (const float*)d_in[0];
    const float* qkvg_w      = (const float*)d_in[1];
    const float* qkvg_gamma  = (const float*)d_in[2];
    const float* qkvg_beta   = (const float*)d_in[3];
    const float* attn_norm_w = (const float*)d_in[4];
    const float* proj_w      = (const float*)d_in[5];
    const float* proj_gamma  = (const float*)d_in[6];
    const float* proj_beta   = (const float*)d_in[7];
    float* out = (float*)d_out;

    float *py, *pattn, *pypre, *pa2, *pb2, *pz;
    __nv_bfloat16 *pkhi, *pklo, *pvhi, *pvlo, *pqthi, *pqtlo, *pxthi, *pxtlo;
    __nv_bfloat16 *pothi, *potlo, *pvkhi, *pvklo, *pwqhi, *pwqlo, *ppwhi, *ppwlo;
    cudaGetSymbolAddress((void**)&py,    g_y);
    cudaGetSymbolAddress((void**)&pattn, g_attn);
    cudaGetSymbolAddress((void**)&pypre, g_ypre);
    cudaGetSymbolAddress((void**)&pa2,   g_a2);
    cudaGetSymbolAddress((void**)&pb2,   g_b2);
    cudaGetSymbolAddress((void**)&pz,    g_z);
    cudaGetSymbolAddress((void**)&pkhi,  g_khi);
    cudaGetSymbolAddress((void**)&pklo,  g_klo);
    cudaGetSymbolAddress((void**)&pvhi,  g_vhi);
    cudaGetSymbolAddress((void**)&pvlo,  g_vlo);
    cudaGetSymbolAddress((void**)&pqthi, g_qthi);
    cudaGetSymbolAddress((void**)&pqtlo, g_qtlo);
    cudaGetSymbolAddress((void**)&pxthi, g_xthi);
    cudaGetSymbolAddress((void**)&pxtlo, g_xtlo);
    cudaGetSymbolAddress((void**)&pothi, g_othi);
    cudaGetSymbolAddress((void**)&potlo, g_otlo);
    cudaGetSymbolAddress((void**)&pvkhi, g_vkhi);
    cudaGetSymbolAddress((void**)&pvklo, g_vklo);
    cudaGetSymbolAddress((void**)&pwqhi, g_wqhi);
    cudaGetSymbolAddress((void**)&pwqlo, g_wqlo);
    cudaGetSymbolAddress((void**)&ppwhi, g_pwhi);
    cudaGetSymbolAddress((void**)&ppwlo, g_pwlo);

    const long long sQKV = (long long)DIM * NPIX;   // 2097152
    const long long sYT  = (long long)NPIX * C4;    // 8388608
    const long long sVK  = (long long)DIM * DIM;    // 262144

    // input conversions
    convert_split<<<4096, 256>>>(qkvg_w, pwqhi, pwqlo, C4 * DIM);
    convert_split<<<1024, 256>>>(proj_w, ppwhi, ppwlo, DIM * DIM);
    transpose_split<<<dim3(128, 16, BATCH), dim3(32, 8)>>>(x, pxthi, pxtlo, DIM, NPIX);
    zero_kernel<<<32, 256>>>();

    // 1) y^T = x^T @ w^T : A = x^T [4096][512]/batch, B = w [2048][512] shared
    gemm_mma<false, false><<<dim3(16, 32, BATCH), 128>>>(
        pxthi, pxtlo, pwqhi, pwqlo, py, nullptr, nullptr,
        2048, 512, sQKV, 0, sYT, 1.f, nullptr);

    // 2) BN1 stats (column-reduce) + finalize
    bn1_colstats<<<dim3(8, 64), 256>>>();
    bn1_finalize<<<8, 256>>>(qkvg_gamma, qkvg_beta);

    // 3) q^T hi/lo; k,v transposed to [d][n] hi/lo + ksum
    q_kernel<<<16384, 256>>>();
    kvt_kernel<<<dim3(128, 16, BATCH), dim3(32, 8)>>>();

    // 4) z (row dots)
    z_kernel<<<4096, 256>>>();

    // 5) vk = (v*s)(k*s)^T : out split bf16
    gemm_mma<false, true><<<dim3(4, 4, BATCH), 128>>>(
        pvhi, pvlo, pkhi, pklo, nullptr, pvkhi, pvklo,
        512, 4096, sQKV, sQKV, sVK, 1.f / 4096.f, nullptr);

    // 6) attn^T = q^T @ vk^T / z  (row-div by z)
    gemm_mma<true, false><<<dim3(4, 32, BATCH), 128>>>(
        pqthi, pqtlo, pvkhi, pvklo, pattn, nullptr, nullptr,
        512, 512, sQKV, sVK, sQKV, 1.f, pz);

    // 7) RMSNorm + gate -> o^T hi/lo
    rmsgate_kernel<<<32768, 128>>>(attn_norm_w);

    // 8) ypre = proj_w @ o : A = w [512][512] shared, B = o^T [4096][512]
    gemm_mma<false, false><<<dim3(32, 4, BATCH), 128>>>(
        ppwhi, ppwlo, pothi, potlo, pypre, nullptr, nullptr,
        4096, 512, 0, sQKV, sQKV, 1.f, nullptr);

    // 9) BN2 + apply
    bn_stats_kernel<<<512, 256>>>(pypre, proj_gamma, proj_beta, pa2, pb2, 512);
    bnapply_kernel<<<16384, 256>>>(out);
}

// round 6
// speedup vs baseline: 2.0986x; 1.1474x over previous
#include <cuda_runtime.h>
#include <cuda_bf16.h>
#include <math.h>
#include <stdint.h>

// ---------------------------------------------------------------------------
// SHMA block: mma.sync bf16 GEMMs (3-term hi/lo split), n-major dataflow,
// 3-stage cp.async pipeline, split-K for the vk GEMM.
// B=8, dim=d=512, N=4096, qkvg=2048.
// ---------------------------------------------------------------------------

#define BATCH 8
#define DIM   512
#define NPIX  4096
#define C4    2048

// ---------------- scratch (static device globals) --------------------------
__device__ float g_y[67108864];                      // y^T (8*4096, 2048) f32
__device__ float g_attn[16777216];                   // attn^T (8*4096, 512) f32
__device__ float g_ypre[16777216];                   // ypre (8, 512, 4096) f32
__device__ float g_vkp[8388608];                     // vk split-K partials (32, 512, 512)
__device__ __nv_bfloat16 g_khi[16777216], g_klo[16777216];   // k [b][d][n]
__device__ __nv_bfloat16 g_vhi[16777216], g_vlo[16777216];   // v [b][d][n]
__device__ __nv_bfloat16 g_qthi[16777216], g_qtlo[16777216]; // q^T [b][n][d]
__device__ __nv_bfloat16 g_xthi[16777216], g_xtlo[16777216]; // x^T [b][n][c]
__device__ __nv_bfloat16 g_othi[16777216], g_otlo[16777216]; // o^T [b][n][d]
__device__ __nv_bfloat16 g_vkhi[2097152], g_vklo[2097152];   // vk [b][d][e]
__device__ __nv_bfloat16 g_wqhi[1048576], g_wqlo[1048576];   // qkvg_w
__device__ __nv_bfloat16 g_pwhi[262144],  g_pwlo[262144];    // proj_w
__device__ float g_a1[2048], g_b1[2048], g_a2[512], g_b2[512];
__device__ float g_s1[2048], g_s2[2048];
__device__ float g_ksum[4096], g_z[32768];

// ---------------- helpers ---------------------------------------------------
__device__ __forceinline__ uint32_t smem_u32(const void* p) {
    uint32_t a;
    asm("{ .reg .u64 t; cvta.to.shared.u64 t, %1; cvt.u32.u64 %0, t; }"
        : "=r"(a) : "l"(p));
    return a;
}
__device__ __forceinline__ void ldsm_x4(uint32_t& r0, uint32_t& r1,
                                        uint32_t& r2, uint32_t& r3,
                                        uint32_t addr) {
    asm volatile("ldmatrix.sync.aligned.m8n8.x4.shared.b16 {%0,%1,%2,%3}, [%4];"
                 : "=r"(r0), "=r"(r1), "=r"(r2), "=r"(r3) : "r"(addr));
}
__device__ __forceinline__ void mma16816(float* c, const uint32_t* a,
                                         uint32_t b0, uint32_t b1) {
    asm volatile(
        "mma.sync.aligned.m16n8k16.row.col.f32.bf16.bf16.f32 "
        "{%0,%1,%2,%3}, {%4,%5,%6,%7}, {%8,%9}, {%0,%1,%2,%3};"
        : "+f"(c[0]), "+f"(c[1]), "+f"(c[2]), "+f"(c[3])
        : "r"(a[0]), "r"(a[1]), "r"(a[2]), "r"(a[3]), "r"(b0), "r"(b1));
}
__device__ __forceinline__ void cpasync16(uint32_t dst, const void* src) {
    asm volatile("cp.async.cg.shared.global [%0], [%1], 16;"
                 :: "r"(dst), "l"(src));
}
#define CP_COMMIT() asm volatile("cp.async.commit_group;" ::: "memory")
#define CP_WAIT(n)  asm volatile("cp.async.wait_group %0;" :: "n"(n) : "memory")

// ---------------------------------------------------------------------------
// mma.sync GEMM: C = alpha * A @ B^T
//   A [M][ldk] hi/lo bf16 rows, B [N][ldk] hi/lo bf16 rows (K-major).
//   Split-K: blockIdx.z = b*kchunks + ks; each chunk covers K elements at
//   column offset ks*K. f32 C is offset zi*sC; bf16 Chi/Clo offset b*sC.
//   3 hi/lo segments: (Ah,Bh), (Ah,Bl), (Al,Bh) in fp32 accum.
//   128x128 CTA tile, BK=32, 128 threads (2x2 warps, 64x64 warp tile),
//   3-stage cp.async pipeline, one __syncthreads per chunk.
//   ZDIV: divide output ROW r by zb[b*4096 + r].  OUTSPLIT: hi/lo bf16 out.
// ---------------------------------------------------------------------------
#define SROW 40                   // padded smem row stride (bf16 elems)
#define BUFB (128 * SROW * 2)     // 10240 bytes per operand stage
#define GSMEM (6 * BUFB + 512)    // 3 stages x (A+B) + zsm

template <bool ZDIV, bool OUTSPLIT>
__global__ void __launch_bounds__(128)
gemm_mma(const __nv_bfloat16* __restrict__ Ahi_, const __nv_bfloat16* __restrict__ Alo_,
         const __nv_bfloat16* __restrict__ Bhi_, const __nv_bfloat16* __restrict__ Blo_,
         float* __restrict__ C_, __nv_bfloat16* __restrict__ Chi_,
         __nv_bfloat16* __restrict__ Clo_,
         int N, int K, int ldk, int kchunks,
         long long sA, long long sB, long long sC,
         float alpha, const float* __restrict__ zb)
{
    extern __shared__ char smem[];
    const int zi = blockIdx.z;
    const int b  = zi / kchunks;
    const int ks = zi - b * kchunks;
    const long long koff = (long long)ks * K;

    const __nv_bfloat16* Ah = Ahi_ + (long long)b * sA + koff;
    const __nv_bfloat16* Al = Alo_ + (long long)b * sA + koff;
    const __nv_bfloat16* Bh = Bhi_ + (long long)b * sB + koff;
    const __nv_bfloat16* Bl = Blo_ + (long long)b * sB + koff;
    const int m0 = blockIdx.y << 7, n0 = blockIdx.x << 7;
    const int tid = threadIdx.x, wid = tid >> 5, lane = tid & 31;
    const int wm = wid & 1, wn = wid >> 1;
    const int tig = lane & 3, grp = lane >> 2;

    const uint32_t sb = smem_u32(smem);
    float* zsm = (float*)(smem + 6 * BUFB);
    if (ZDIV) zsm[tid] = 1.f / zb[(long long)b * 4096 + m0 + tid];

    const int K32 = K >> 5;
    const int CH = 3 * K32;

    float acc[4][8][4];
#pragma unroll
    for (int i = 0; i < 4; i++)
#pragma unroll
        for (int j = 0; j < 8; j++)
#pragma unroll
            for (int t = 0; t < 4; t++) acc[i][j][t] = 0.f;

    // cp.async loader: 4x16B for A + 4x16B for B per thread per chunk
    auto load = [&](int c, int bi) {
        int s = c / K32;
        int kc = c - s * K32;
        const __nv_bfloat16* Ap = (s == 2) ? Al : Ah;
        const __nv_bfloat16* Bp = (s == 1) ? Bl : Bh;
        long long kp = (long long)kc << 5;
        uint32_t ab = sb + (uint32_t)bi * BUFB;
        uint32_t bb = sb + (uint32_t)(3 + bi) * BUFB;
#pragma unroll
        for (int i = 0; i < 4; i++) {
            int slot = tid + (i << 7);
            int row = slot >> 2, u = slot & 3;
            uint32_t d = (uint32_t)(row * (SROW * 2) + (u << 4));
            cpasync16(ab + d, Ap + (long long)(m0 + row) * ldk + kp + (u << 3));
            cpasync16(bb + d, Bp + (long long)(n0 + row) * ldk + kp + (u << 3));
        }
        CP_COMMIT();
    };

    load(0, 0);
    if (CH > 1) load(1, 1);

    const uint32_t lrow16 = lane & 15;
    const uint32_t lcol8 = (lane >> 4) << 3;

    int buf = 0;
    for (int c = 0; c < CH; c++) {
        if (c + 1 < CH) { CP_WAIT(1); } else { CP_WAIT(0); }
        __syncthreads();
        if (c + 2 < CH) {
            int nb = buf + 2; if (nb >= 3) nb -= 3;
            load(c + 2, nb);
        }

        uint32_t abase = sb + (uint32_t)buf * BUFB;
        uint32_t bbase = sb + (uint32_t)(3 + buf) * BUFB;
#pragma unroll
        for (int ko2 = 0; ko2 < 2; ko2++) {
            const uint32_t ko = ko2 << 4;
            uint32_t a[4][4];
#pragma unroll
            for (int mi = 0; mi < 4; mi++) {
                uint32_t ad = abase +
                    (((wm << 6) + (mi << 4) + lrow16) * SROW + ko + lcol8) * 2;
                ldsm_x4(a[mi][0], a[mi][1], a[mi][2], a[mi][3], ad);
            }
            uint32_t bf[4][4];
#pragma unroll
            for (int nb = 0; nb < 4; nb++) {
                uint32_t bd = bbase +
                    (((wn << 6) + (nb << 4) + lrow16) * SROW + ko + lcol8) * 2;
                ldsm_x4(bf[nb][0], bf[nb][1], bf[nb][2], bf[nb][3], bd);
            }
#pragma unroll
            for (int mi = 0; mi < 4; mi++)
#pragma unroll
                for (int ni = 0; ni < 8; ni++) {
                    int nb = ni >> 1, hf = ni & 1;
                    mma16816(acc[mi][ni], a[mi], bf[nb][hf], bf[nb][hf + 2]);
                }
        }
        buf++; if (buf == 3) buf = 0;
    }

    // epilogue
    float* C = C_ + (long long)zi * sC;
    __nv_bfloat16* Chi = Chi_ + (long long)b * sC;
    __nv_bfloat16* Clo = Clo_ + (long long)b * sC;
#pragma unroll
    for (int mi = 0; mi < 4; mi++) {
        int rl = (wm << 6) + (mi << 4) + grp;
        int row = m0 + rl;
        float zr0 = 1.f, zr1 = 1.f;
        if (ZDIV) { zr0 = zsm[rl]; zr1 = zsm[rl + 8]; }
#pragma unroll
        for (int ni = 0; ni < 8; ni++) {
            int col = n0 + (wn << 6) + (ni << 3) + (tig << 1);
            float v0 = acc[mi][ni][0] * alpha;
            float v1 = acc[mi][ni][1] * alpha;
            float v2 = acc[mi][ni][2] * alpha;
            float v3 = acc[mi][ni][3] * alpha;
            if (ZDIV) { v0 *= zr0; v1 *= zr0; v2 *= zr1; v3 *= zr1; }
            if (OUTSPLIT) {
                __nv_bfloat16 h0 = __float2bfloat16(v0);
                __nv_bfloat16 h1 = __float2bfloat16(v1);
                __nv_bfloat16 h2 = __float2bfloat16(v2);
                __nv_bfloat16 h3 = __float2bfloat16(v3);
                *(__nv_bfloat162*)(Chi + (long long)row * N + col) =
                    __halves2bfloat162(h0, h1);
                *(__nv_bfloat162*)(Chi + (long long)(row + 8) * N + col) =
                    __halves2bfloat162(h2, h3);
                *(__nv_bfloat162*)(Clo + (long long)row * N + col) =
                    __halves2bfloat162(__float2bfloat16(v0 - __bfloat162float(h0)),
                                       __float2bfloat16(v1 - __bfloat162float(h1)));
                *(__nv_bfloat162*)(Clo + (long long)(row + 8) * N + col) =
                    __halves2bfloat162(__float2bfloat16(v2 - __bfloat162float(h2)),
                                       __float2bfloat16(v3 - __bfloat162float(h3)));
            } else {
                float2 p0; p0.x = v0; p0.y = v1;
                float2 p1; p1.x = v2; p1.y = v3;
                *(float2*)(C + (long long)row * N + col) = p0;
                *(float2*)(C + (long long)(row + 8) * N + col) = p1;
            }
        }
    }
}

// ---------------------------------------------------------------------------
// vk split-K reduce: vk[b] = alpha * sum_ks vkp[b*4+ks]; emit hi/lo bf16
// ---------------------------------------------------------------------------
__global__ void vkred_kernel()
{
    long long i4 = (long long)(blockIdx.x * 256 + threadIdx.x) * 4;
    int b = (int)(i4 >> 18);
    long long off = i4 & 262143;
    const float* p = g_vkp + ((long long)b * 4) * 262144 + off;
    float4 s0 = *(const float4*)p;
    float4 s1 = *(const float4*)(p + 262144);
    float4 s2 = *(const float4*)(p + 2 * 262144);
    float4 s3 = *(const float4*)(p + 3 * 262144);
    const float al = 1.f / 4096.f;
    float v[4];
    v[0] = ((s0.x + s1.x) + (s2.x + s3.x)) * al;
    v[1] = ((s0.y + s1.y) + (s2.y + s3.y)) * al;
    v[2] = ((s0.z + s1.z) + (s2.z + s3.z)) * al;
    v[3] = ((s0.w + s1.w) + (s2.w + s3.w)) * al;
    __nv_bfloat16 h[4], l[4];
#pragma unroll
    for (int j = 0; j < 4; j++) {
        h[j] = __float2bfloat16(v[j]);
        l[j] = __float2bfloat16(v[j] - __bfloat162float(h[j]));
    }
    *(__nv_bfloat162*)(g_vkhi + i4)     = __halves2bfloat162(h[0], h[1]);
    *(__nv_bfloat162*)(g_vkhi + i4 + 2) = __halves2bfloat162(h[2], h[3]);
    *(__nv_bfloat162*)(g_vklo + i4)     = __halves2bfloat162(l[0], l[1]);
    *(__nv_bfloat162*)(g_vklo + i4 + 2) = __halves2bfloat162(l[2], l[3]);
}

// ---------------------------------------------------------------------------
// elementwise / reduction kernels
// ---------------------------------------------------------------------------
__global__ void zero_kernel()
{
    int i = blockIdx.x * 256 + threadIdx.x;
    if (i < 2048) { g_s1[i] = 0.f; g_s2[i] = 0.f; }
    if (i < 4096) g_ksum[i] = 0.f;
}

__global__ void bn1_colstats()
{
    int c = blockIdx.x * 256 + threadIdx.x;
    int r0 = blockIdx.y * 512;
    const float* p = g_y + (long long)r0 * C4 + c;
    float s1 = 0.f, s2 = 0.f;
#pragma unroll 4
    for (int r = 0; r < 512; r++) {
        float v = p[(long long)r * C4];
        s1 += v; s2 += v * v;
    }
    atomicAdd(&g_s1[c], s1);
    atomicAdd(&g_s2[c], s2);
}

__global__ void bn1_finalize(const float* __restrict__ gamma,
                             const float* __restrict__ beta)
{
    int c = blockIdx.x * 256 + threadIdx.x;
    const float inv = 1.f / (BATCH * NPIX);
    float mean = g_s1[c] * inv;
    float var = g_s2[c] * inv - mean * mean;
    float av = gamma[c] * rsqrtf(var + 1e-5f);
    g_a1[c] = av;
    g_b1[c] = beta[c] - mean * av;
}

__global__ void q_kernel()
{
    int i = blockIdx.x * 256 + threadIdx.x;
    int r = i >> 7;
    int dg = (i & 127) << 2;
    float4 y4 = *(const float4*)(g_y + (long long)r * C4 + dg);
    float4 a4 = *(const float4*)(g_a1 + dg);
    float4 b4 = *(const float4*)(g_b1 + dg);
    float q0 = 1.f / (1.f + expf(-(a4.x * y4.x + b4.x)));
    float q1 = 1.f / (1.f + expf(-(a4.y * y4.y + b4.y)));
    float q2 = 1.f / (1.f + expf(-(a4.z * y4.z + b4.z)));
    float q3 = 1.f / (1.f + expf(-(a4.w * y4.w + b4.w)));
    __nv_bfloat16 h0 = __float2bfloat16(q0), h1 = __float2bfloat16(q1);
    __nv_bfloat16 h2 = __float2bfloat16(q2), h3 = __float2bfloat16(q3);
    long long o = (long long)r * DIM + dg;
    *(__nv_bfloat162*)(g_qthi + o)     = __halves2bfloat162(h0, h1);
    *(__nv_bfloat162*)(g_qthi + o + 2) = __halves2bfloat162(h2, h3);
    *(__nv_bfloat162*)(g_qtlo + o) =
        __halves2bfloat162(__float2bfloat16(q0 - __bfloat162float(h0)),
                           __float2bfloat16(q1 - __bfloat162float(h1)));
    *(__nv_bfloat162*)(g_qtlo + o + 2) =
        __halves2bfloat162(__float2bfloat16(q2 - __bfloat162float(h2)),
                           __float2bfloat16(q3 - __bfloat162float(h3)));
}

__global__ void kvt_kernel()
{
    __shared__ float tk[32][33], tv[32][33];
    int bz = blockIdx.z;
    int n0 = blockIdx.x << 5, d0 = blockIdx.y << 5;
    int tx = threadIdx.x, ty = threadIdx.y;
    float ak = g_a1[512 + d0 + tx],  bk = g_b1[512 + d0 + tx];
    float av = g_a1[1024 + d0 + tx], bv = g_b1[1024 + d0 + tx];
    long long rowbase = ((long long)(bz << 12) + n0) * C4;
#pragma unroll
    for (int i = 0; i < 4; i++) {
        long long rr = rowbase + (long long)(ty + 8 * i) * C4;
        float kraw = g_y[rr + 512 + d0 + tx];
        float vraw = g_y[rr + 1024 + d0 + tx];
        tk[ty + 8 * i][tx] = 1.f / (1.f + expf(-(ak * kraw + bk)));
        tv[ty + 8 * i][tx] = av * vraw + bv;
    }
    __syncthreads();
#pragma unroll
    for (int i = 0; i < 4; i++) {
        int d = d0 + ty + 8 * i;
        int n = n0 + tx;
        float ks = tk[tx][ty + 8 * i];
        float vs = tv[tx][ty + 8 * i];
        long long o = ((long long)(bz << 9) + d) * NPIX + n;
        __nv_bfloat16 kh = __float2bfloat16(ks);
        g_khi[o] = kh;
        g_klo[o] = __float2bfloat16(ks - __bfloat162float(kh));
        __nv_bfloat16 vh = __float2bfloat16(vs);
        g_vhi[o] = vh;
        g_vlo[o] = __float2bfloat16(vs - __bfloat162float(vh));
        float s = ks;
#pragma unroll
        for (int off = 16; off > 0; off >>= 1)
            s += __shfl_down_sync(0xffffffffu, s, off);
        if (tx == 0) atomicAdd(&g_ksum[(bz << 9) + d], s);
    }
}

__global__ void z_kernel()
{
    __shared__ float km[512];
    int r0 = blockIdx.x << 3;
    int bb = r0 >> 12;
    for (int i = threadIdx.x; i < 512; i += 256)
        km[i] = g_ksum[(bb << 9) + i] * (1.f / NPIX);
    __syncthreads();
    int w = threadIdx.x >> 5, lane = threadIdx.x & 31;
    int r = r0 + w;
    const __nv_bfloat16* qh = g_qthi + (long long)r * DIM;
    const __nv_bfloat16* ql = g_qtlo + (long long)r * DIM;
    float s = 0.f;
#pragma unroll
    for (int i = 0; i < 16; i++) {
        int d = lane + (i << 5);
        s += km[d] * (__bfloat162float(qh[d]) + __bfloat162float(ql[d]));
    }
#pragma unroll
    for (int off = 16; off > 0; off >>= 1)
        s += __shfl_down_sync(0xffffffffu, s, off);
    if (lane == 0) g_z[r] = s + 5e-4f;
}

__global__ void rmsgate_kernel(const float* __restrict__ anw)
{
    __shared__ float red[4];
    int r = blockIdx.x;
    int t = threadIdx.x;
    int dg = t << 2;
    const float* at = g_attn + (long long)r * DIM + dg;
    float4 a = *(const float4*)at;
    float ss = a.x * a.x + a.y * a.y + a.z * a.z + a.w * a.w;
    int lane = t & 31, w = t >> 5;
#pragma unroll
    for (int off = 16; off > 0; off >>= 1)
        ss += __shfl_down_sync(0xffffffffu, ss, off);
    if (lane == 0) red[w] = ss;
    __syncthreads();
    float tot = red[0] + red[1] + red[2] + red[3];
    float rms = rsqrtf(tot * (1.f / DIM) + 1e-6f);

    float4 ga = *(const float4*)(g_a1 + 1536 + dg);
    float4 gb = *(const float4*)(g_b1 + 1536 + dg);
    float4 yg = *(const float4*)(g_y + (long long)r * C4 + 1536 + dg);
    float4 wn = *(const float4*)(anw + dg);
    float g0 = ga.x * yg.x + gb.x, g1 = ga.y * yg.y + gb.y;
    float g2 = ga.z * yg.z + gb.z, g3 = ga.w * yg.w + gb.w;
    float o0 = a.x * rms * wn.x * (g0 / (1.f + expf(-g0)));
    float o1 = a.y * rms * wn.y * (g1 / (1.f + expf(-g1)));
    float o2 = a.z * rms * wn.z * (g2 / (1.f + expf(-g2)));
    float o3 = a.w * rms * wn.w * (g3 / (1.f + expf(-g3)));
    __nv_bfloat16 h0 = __float2bfloat16(o0), h1 = __float2bfloat16(o1);
    __nv_bfloat16 h2 = __float2bfloat16(o2), h3 = __float2bfloat16(o3);
    long long o = (long long)r * DIM + dg;
    *(__nv_bfloat162*)(g_othi + o)     = __halves2bfloat162(h0, h1);
    *(__nv_bfloat162*)(g_othi + o + 2) = __halves2bfloat162(h2, h3);
    *(__nv_bfloat162*)(g_otlo + o) =
        __halves2bfloat162(__float2bfloat16(o0 - __bfloat162float(h0)),
                           __float2bfloat16(o1 - __bfloat162float(h1)));
    *(__nv_bfloat162*)(g_otlo + o + 2) =
        __halves2bfloat162(__float2bfloat16(o2 - __bfloat162float(h2)),
                           __float2bfloat16(o3 - __bfloat162float(h3)));
}

__device__ __forceinline__ void blockReduce2(float& s1, float& s2)
{
    __shared__ float sh1[32], sh2[32];
    int lane = threadIdx.x & 31, w = threadIdx.x >> 5;
#pragma unroll
    for (int o = 16; o > 0; o >>= 1) {
        s1 += __shfl_down_sync(0xffffffffu, s1, o);
        s2 += __shfl_down_sync(0xffffffffu, s2, o);
    }
    if (lane == 0) { sh1[w] = s1; sh2[w] = s2; }
    __syncthreads();
    int nw = blockDim.x >> 5;
    if (w == 0) {
        s1 = lane < nw ? sh1[lane] : 0.f;
        s2 = lane < nw ? sh2[lane] : 0.f;
#pragma unroll
        for (int o = 16; o > 0; o >>= 1) {
            s1 += __shfl_down_sync(0xffffffffu, s1, o);
            s2 += __shfl_down_sync(0xffffffffu, s2, o);
        }
    }
}

__global__ void bn_stats_kernel(const float* __restrict__ y,
                                const float* __restrict__ gamma,
                                const float* __restrict__ beta,
                                float* __restrict__ a, float* __restrict__ bb,
                                int Cdim)
{
    int c = blockIdx.x;
    float s1 = 0.f, s2 = 0.f;
    for (int i = threadIdx.x; i < BATCH * NPIX; i += blockDim.x) {
        int bi = i >> 12, n = i & 4095;
        float v = y[((long long)bi * Cdim + c) * NPIX + n];
        s1 += v; s2 += v * v;
    }
    blockReduce2(s1, s2);
    if (threadIdx.x == 0) {
        const float inv = 1.f / (BATCH * NPIX);
        float mean = s1 * inv;
        float var = s2 * inv - mean * mean;
        float av = gamma[c] * rsqrtf(var + 1e-5f);
        a[c] = av;
        bb[c] = beta[c] - mean * av;
    }
}

__global__ void bnapply_kernel(float* __restrict__ out)
{
    long long i = (long long)(blockIdx.x * blockDim.x + threadIdx.x) * 4;
    int c = (int)((i >> 12) & 511);
    float a = g_a2[c], bb = g_b2[c];
    float4 v = *reinterpret_cast<const float4*>(g_ypre + i);
    v.x = a * v.x + bb; v.y = a * v.y + bb;
    v.z = a * v.z + bb; v.w = a * v.w + bb;
    *reinterpret_cast<float4*>(out + i) = v;
}

__global__ void convert_split(const float* __restrict__ s,
                              __nv_bfloat16* __restrict__ hi,
                              __nv_bfloat16* __restrict__ lo, int n)
{
    int i = blockIdx.x * blockDim.x + threadIdx.x;
    if (i < n) {
        float v = s[i];
        __nv_bfloat16 h = __float2bfloat16(v);
        hi[i] = h;
        lo[i] = __float2bfloat16(v - __bfloat162float(h));
    }
}

__global__ void transpose_split(const float* __restrict__ src,
                                __nv_bfloat16* __restrict__ dhi,
                                __nv_bfloat16* __restrict__ dlo, int R, int Cc)
{
    __shared__ float t[32][33];
    int b = blockIdx.z;
    long long o = (long long)b * R * Cc;
    src += o; dhi += o; dlo += o;
    int c0 = blockIdx.x * 32, r0 = blockIdx.y * 32;
    int tx = threadIdx.x, ty = threadIdx.y;
#pragma unroll
    for (int i = 0; i < 4; i++)
        t[ty + 8 * i][tx] = src[(long long)(r0 + ty + 8 * i) * Cc + c0 + tx];
    __syncthreads();
#pragma unroll
    for (int i = 0; i < 4; i++) {
        int cc = c0 + ty + 8 * i;
        float v = t[tx][ty + 8 * i];
        __nv_bfloat16 h = __float2bfloat16(v);
        dhi[(long long)cc * R + r0 + tx] = h;
        dlo[(long long)cc * R + r0 + tx] = __float2bfloat16(v - __bfloat162float(h));
    }
}

// ---------------------------------------------------------------------------
extern "C" void kernel_launch(void* const* d_in, const int* in_sizes, int n_in,
                              void* d_out, int out_size)
{
    const float* x           = (const float*)d_in[0];
    const float* qkvg_w      = (const float*)d_in[1];
    const float* qkvg_gamma  = (const float*)d_in[2];
    const float* qkvg_beta   = (const float*)d_in[3];
    const float* attn_norm_w = (const float*)d_in[4];
    const float* proj_w      = (const float*)d_in[5];
    const float* proj_gamma  = (const float*)d_in[6];
    const float* proj_beta   = (const float*)d_in[7];
    float* out = (float*)d_out;

    cudaFuncSetAttribute(gemm_mma<false, false>,
                         cudaFuncAttributeMaxDynamicSharedMemorySize, GSMEM);
    cudaFuncSetAttribute(gemm_mma<true, false>,
                         cudaFuncAttributeMaxDynamicSharedMemorySize, GSMEM);
    cudaFuncSetAttribute(gemm_mma<false, true>,
                         cudaFuncAttributeMaxDynamicSharedMemorySize, GSMEM);

    float *py, *pattn, *pypre, *pvkp, *pa2, *pb2, *pz;
    __nv_bfloat16 *pkhi, *pklo, *pvhi, *pvlo, *pqthi, *pqtlo, *pxthi, *pxtlo;
    __nv_bfloat16 *pothi, *potlo, *pvkhi, *pvklo, *pwqhi, *pwqlo, *ppwhi, *ppwlo;
    cudaGetSymbolAddress((void**)&py,    g_y);
    cudaGetSymbolAddress((void**)&pattn, g_attn);
    cudaGetSymbolAddress((void**)&pypre, g_ypre);
    cudaGetSymbolAddress((void**)&pvkp,  g_vkp);
    cudaGetSymbolAddress((void**)&pa2,   g_a2);
    cudaGetSymbolAddress((void**)&pb2,   g_b2);
    cudaGetSymbolAddress((void**)&pz,    g_z);
    cudaGetSymbolAddress((void**)&pkhi,  g_khi);
    cudaGetSymbolAddress((void**)&pklo,  g_klo);
    cudaGetSymbolAddress((void**)&pvhi,  g_vhi);
    cudaGetSymbolAddress((void**)&pvlo,  g_vlo);
    cudaGetSymbolAddress((void**)&pqthi, g_qthi);
    cudaGetSymbolAddress((void**)&pqtlo, g_qtlo);
    cudaGetSymbolAddress((void**)&pxthi, g_xthi);
    cudaGetSymbolAddress((void**)&pxtlo, g_xtlo);
    cudaGetSymbolAddress((void**)&pothi, g_othi);
    cudaGetSymbolAddress((void**)&potlo, g_otlo);
    cudaGetSymbolAddress((void**)&pvkhi, g_vkhi);
    cudaGetSymbolAddress((void**)&pvklo, g_vklo);
    cudaGetSymbolAddress((void**)&pwqhi, g_wqhi);
    cudaGetSymbolAddress((void**)&pwqlo, g_wqlo);
    cudaGetSymbolAddress((void**)&ppwhi, g_pwhi);
    cudaGetSymbolAddress((void**)&ppwlo, g_pwlo);

    const long long sQKV = (long long)DIM * NPIX;   // 2097152
    const long long sYT  = (long long)NPIX * C4;    // 8388608
    const long long sVK  = (long long)DIM * DIM;    // 262144

    // launches 0..4 (puts gemm1 at ncu capture slot -s 5)
    zero_kernel<<<32, 256>>>();
    convert_split<<<2048, 256>>>(qkvg_w, pwqhi, pwqlo, C4 * DIM / 2);
    convert_split<<<2048, 256>>>(qkvg_w + C4 * DIM / 2, pwqhi + C4 * DIM / 2,
                                 pwqlo + C4 * DIM / 2, C4 * DIM / 2);
    convert_split<<<1024, 256>>>(proj_w, ppwhi, ppwlo, DIM * DIM);
    transpose_split<<<dim3(128, 16, BATCH), dim3(32, 8)>>>(x, pxthi, pxtlo, DIM, NPIX);

    // 1) y^T = x^T @ w^T : A = x^T [4096][512]/batch, B = w [2048][512] shared
    gemm_mma<false, false><<<dim3(16, 32, BATCH), 128, GSMEM>>>(
        pxthi, pxtlo, pwqhi, pwqlo, py, nullptr, nullptr,
        2048, 512, 512, 1, sQKV, 0, sYT, 1.f, nullptr);

    // 2) BN1 stats + finalize
    bn1_colstats<<<dim3(8, 64), 256>>>();
    bn1_finalize<<<8, 256>>>(qkvg_gamma, qkvg_beta);

    // 3) q^T hi/lo; k,v -> [d][n] hi/lo + ksum
    q_kernel<<<16384, 256>>>();
    kvt_kernel<<<dim3(128, 16, BATCH), dim3(32, 8)>>>();

    // 4) z
    z_kernel<<<4096, 256>>>();

    // 5) vk = v @ k^T, split-K x4 (Kc=1024, ldk=4096), f32 partials; reduce
    gemm_mma<false, false><<<dim3(4, 4, BATCH * 4), 128, GSMEM>>>(
        pvhi, pvlo, pkhi, pklo, pvkp, nullptr, nullptr,
        512, 1024, 4096, 4, sQKV, sQKV, sVK, 1.f, nullptr);
    vkred_kernel<<<2048, 256>>>();

    // 6) attn^T = q^T @ vk^T / z (row-div by z)
    gemm_mma<true, false><<<dim3(4, 32, BATCH), 128, GSMEM>>>(
        pqthi, pqtlo, pvkhi, pvklo, pattn, nullptr, nullptr,
        512, 512, 512, 1, sQKV, sVK, sQKV, 1.f, pz);

    // 7) RMSNorm + gate -> o^T hi/lo
    rmsgate_kernel<<<32768, 128>>>(attn_norm_w);

    // 8) ypre = proj_w @ o : A = w [512][512] shared, B = o^T [4096][512]
    gemm_mma<false, false><<<dim3(32, 4, BATCH), 128, GSMEM>>>(
        ppwhi, ppwlo, pothi, potlo, pypre, nullptr, nullptr,
        4096, 512, 512, 1, 0, sQKV, sQKV, 1.f, nullptr);

    // 9) BN2 + apply
    bn_stats_kernel<<<512, 256>>>(pypre, proj_gamma, proj_beta, pa2, pb2, 512);
    bnapply_kernel<<<16384, 256>>>(out);
}

// round 7
// speedup vs baseline: 2.2112x; 1.0537x over previous
#include <cuda_runtime.h>
#include <cuda_bf16.h>
#include <math.h>
#include <stdint.h>

// ---------------------------------------------------------------------------
// SHMA block: mma.sync bf16 GEMMs (3-term hi/lo split), n-major dataflow,
// 3-stage cp.async pipeline, BN1 stats fused into GEMM1 epilogue, y/attn
// stored as bf16 hi/lo. B=8, dim=d=512, N=4096, qkvg=2048.
// ---------------------------------------------------------------------------

#define BATCH 8
#define DIM   512
#define NPIX  4096
#define C4    2048

// ---------------- scratch (static device globals) --------------------------
__device__ __nv_bfloat16 g_ythi[67108864], g_ytlo[67108864]; // y^T (8*4096,2048)
__device__ __nv_bfloat16 g_athi[16777216], g_atlo[16777216]; // attn^T (8*4096,512)
__device__ float g_ypre[16777216];                   // ypre (8, 512, 4096) f32
__device__ float g_vkp[8388608];                     // vk split-K partials
__device__ __nv_bfloat16 g_khi[16777216], g_klo[16777216];   // k [b][d][n]
__device__ __nv_bfloat16 g_vhi[16777216], g_vlo[16777216];   // v [b][d][n]
__device__ __nv_bfloat16 g_qthi[16777216], g_qtlo[16777216]; // q^T [b][n][d]
__device__ __nv_bfloat16 g_xthi[16777216], g_xtlo[16777216]; // x^T [b][n][c]
__device__ __nv_bfloat16 g_othi[16777216], g_otlo[16777216]; // o^T [b][n][d]
__device__ __nv_bfloat16 g_vkhi[2097152], g_vklo[2097152];   // vk [b][d][e]
__device__ __nv_bfloat16 g_wqhi[1048576], g_wqlo[1048576];   // qkvg_w
__device__ __nv_bfloat16 g_pwhi[262144],  g_pwlo[262144];    // proj_w
__device__ float g_a1[2048], g_b1[2048], g_a2[512], g_b2[512];
__device__ float g_s1[2048], g_s2[2048];
__device__ float g_ksum[4096], g_z[32768];

// ---------------- helpers ---------------------------------------------------
__device__ __forceinline__ uint32_t smem_u32(const void* p) {
    uint32_t a;
    asm("{ .reg .u64 t; cvta.to.shared.u64 t, %1; cvt.u32.u64 %0, t; }"
        : "=r"(a) : "l"(p));
    return a;
}
__device__ __forceinline__ void ldsm_x4(uint32_t& r0, uint32_t& r1,
                                        uint32_t& r2, uint32_t& r3,
                                        uint32_t addr) {
    asm volatile("ldmatrix.sync.aligned.m8n8.x4.shared.b16 {%0,%1,%2,%3}, [%4];"
                 : "=r"(r0), "=r"(r1), "=r"(r2), "=r"(r3) : "r"(addr));
}
__device__ __forceinline__ void mma16816(float* c, const uint32_t* a,
                                         uint32_t b0, uint32_t b1) {
    asm volatile(
        "mma.sync.aligned.m16n8k16.row.col.f32.bf16.bf16.f32 "
        "{%0,%1,%2,%3}, {%4,%5,%6,%7}, {%8,%9}, {%0,%1,%2,%3};"
        : "+f"(c[0]), "+f"(c[1]), "+f"(c[2]), "+f"(c[3])
        : "r"(a[0]), "r"(a[1]), "r"(a[2]), "r"(a[3]), "r"(b0), "r"(b1));
}
__device__ __forceinline__ void cpasync16(uint32_t dst, const void* src) {
    asm volatile("cp.async.cg.shared.global [%0], [%1], 16;"
                 :: "r"(dst), "l"(src));
}
#define CP_COMMIT() asm volatile("cp.async.commit_group;" ::: "memory")
#define CP_WAIT(n)  asm volatile("cp.async.wait_group %0;" :: "n"(n) : "memory")

__device__ __forceinline__ __nv_bfloat162 split_hi2(float a, float b,
                                                    __nv_bfloat162& lo) {
    __nv_bfloat16 h0 = __float2bfloat16(a), h1 = __float2bfloat16(b);
    lo = __halves2bfloat162(__float2bfloat16(a - __bfloat162float(h0)),
                            __float2bfloat16(b - __bfloat162float(h1)));
    return __halves2bfloat162(h0, h1);
}

// ---------------------------------------------------------------------------
// mma.sync GEMM: C = alpha * A @ B^T  (A [M][ldk], B [N][ldk] hi/lo bf16)
// 3 hi/lo segments (Ah,Bh),(Ah,Bl),(Al,Bh); 128x128 CTA tile, BK=32,
// 128 threads (2x2 warps, 64x64 warp tiles), 3-stage cp.async pipeline.
// Split-K via blockIdx.z = b*kchunks + ks (f32 C offset by zi*sC).
// ZDIV: row-divide by zb. OUTSPLIT: hi/lo bf16 out. STATS: fused per-column
// sum / sum-of-squares atomics into g_s1/g_s2 (for BN over columns).
// ---------------------------------------------------------------------------
#define SROW 40
#define BUFB (128 * SROW * 2)
#define GSMEM (6 * BUFB + 512)

template <bool ZDIV, bool OUTSPLIT, bool STATS>
__global__ void __launch_bounds__(128)
gemm_mma(const __nv_bfloat16* __restrict__ Ahi_, const __nv_bfloat16* __restrict__ Alo_,
         const __nv_bfloat16* __restrict__ Bhi_, const __nv_bfloat16* __restrict__ Blo_,
         float* __restrict__ C_, __nv_bfloat16* __restrict__ Chi_,
         __nv_bfloat16* __restrict__ Clo_,
         int N, int K, int ldk, int kchunks,
         long long sA, long long sB, long long sC,
         float alpha, const float* __restrict__ zb)
{
    extern __shared__ char smem[];
    const int zi = blockIdx.z;
    const int b  = zi / kchunks;
    const int ks = zi - b * kchunks;
    const long long koff = (long long)ks * K;

    const __nv_bfloat16* Ah = Ahi_ + (long long)b * sA + koff;
    const __nv_bfloat16* Al = Alo_ + (long long)b * sA + koff;
    const __nv_bfloat16* Bh = Bhi_ + (long long)b * sB + koff;
    const __nv_bfloat16* Bl = Blo_ + (long long)b * sB + koff;
    const int m0 = blockIdx.y << 7, n0 = blockIdx.x << 7;
    const int tid = threadIdx.x, wid = tid >> 5, lane = tid & 31;
    const int wm = wid & 1, wn = wid >> 1;
    const int tig = lane & 3, grp = lane >> 2;

    const uint32_t sb = smem_u32(smem);
    float* zsm = (float*)(smem + 6 * BUFB);
    if (ZDIV) zsm[tid] = 1.f / zb[(long long)b * 4096 + m0 + tid];

    const int K32 = K >> 5;
    const int CH = 3 * K32;

    float acc[4][8][4];
#pragma unroll
    for (int i = 0; i < 4; i++)
#pragma unroll
        for (int j = 0; j < 8; j++)
#pragma unroll
            for (int t = 0; t < 4; t++) acc[i][j][t] = 0.f;

    auto load = [&](int c, int bi) {
        int s = c / K32;
        int kc = c - s * K32;
        const __nv_bfloat16* Ap = (s == 2) ? Al : Ah;
        const __nv_bfloat16* Bp = (s == 1) ? Bl : Bh;
        long long kp = (long long)kc << 5;
        uint32_t ab = sb + (uint32_t)bi * BUFB;
        uint32_t bb = sb + (uint32_t)(3 + bi) * BUFB;
#pragma unroll
        for (int i = 0; i < 4; i++) {
            int slot = tid + (i << 7);
            int row = slot >> 2, u = slot & 3;
            uint32_t d = (uint32_t)(row * (SROW * 2) + (u << 4));
            cpasync16(ab + d, Ap + (long long)(m0 + row) * ldk + kp + (u << 3));
            cpasync16(bb + d, Bp + (long long)(n0 + row) * ldk + kp + (u << 3));
        }
        CP_COMMIT();
    };

    load(0, 0);
    if (CH > 1) load(1, 1);

    const uint32_t lrow16 = lane & 15;
    const uint32_t lcol8 = (lane >> 4) << 3;

    int buf = 0;
    for (int c = 0; c < CH; c++) {
        if (c + 1 < CH) { CP_WAIT(1); } else { CP_WAIT(0); }
        __syncthreads();
        if (c + 2 < CH) {
            int nb = buf + 2; if (nb >= 3) nb -= 3;
            load(c + 2, nb);
        }

        uint32_t abase = sb + (uint32_t)buf * BUFB;
        uint32_t bbase = sb + (uint32_t)(3 + buf) * BUFB;
#pragma unroll
        for (int ko2 = 0; ko2 < 2; ko2++) {
            const uint32_t ko = ko2 << 4;
            uint32_t a[4][4];
#pragma unroll
            for (int mi = 0; mi < 4; mi++) {
                uint32_t ad = abase +
                    (((wm << 6) + (mi << 4) + lrow16) * SROW + ko + lcol8) * 2;
                ldsm_x4(a[mi][0], a[mi][1], a[mi][2], a[mi][3], ad);
            }
            uint32_t bf[4][4];
#pragma unroll
            for (int nb = 0; nb < 4; nb++) {
                uint32_t bd = bbase +
                    (((wn << 6) + (nb << 4) + lrow16) * SROW + ko + lcol8) * 2;
                ldsm_x4(bf[nb][0], bf[nb][1], bf[nb][2], bf[nb][3], bd);
            }
#pragma unroll
            for (int mi = 0; mi < 4; mi++)
#pragma unroll
                for (int ni = 0; ni < 8; ni++) {
                    int nb = ni >> 1, hf = ni & 1;
                    mma16816(acc[mi][ni], a[mi], bf[nb][hf], bf[nb][hf + 2]);
                }
        }
        buf++; if (buf == 3) buf = 0;
    }

    // epilogue
    float* C = C_ + (long long)zi * sC;
    __nv_bfloat16* Chi = Chi_ + (long long)b * sC;
    __nv_bfloat16* Clo = Clo_ + (long long)b * sC;
    float cs1[8][2], cs2[8][2];
    if (STATS) {
#pragma unroll
        for (int ni = 0; ni < 8; ni++) {
            cs1[ni][0] = cs1[ni][1] = 0.f;
            cs2[ni][0] = cs2[ni][1] = 0.f;
        }
    }
#pragma unroll
    for (int mi = 0; mi < 4; mi++) {
        int rl = (wm << 6) + (mi << 4) + grp;
        int row = m0 + rl;
        float zr0 = 1.f, zr1 = 1.f;
        if (ZDIV) { zr0 = zsm[rl]; zr1 = zsm[rl + 8]; }
#pragma unroll
        for (int ni = 0; ni < 8; ni++) {
            int col = n0 + (wn << 6) + (ni << 3) + (tig << 1);
            float v0 = acc[mi][ni][0] * alpha;
            float v1 = acc[mi][ni][1] * alpha;
            float v2 = acc[mi][ni][2] * alpha;
            float v3 = acc[mi][ni][3] * alpha;
            if (ZDIV) { v0 *= zr0; v1 *= zr0; v2 *= zr1; v3 *= zr1; }
            if (STATS) {
                cs1[ni][0] += v0 + v2;
                cs1[ni][1] += v1 + v3;
                cs2[ni][0] += v0 * v0 + v2 * v2;
                cs2[ni][1] += v1 * v1 + v3 * v3;
            }
            if (OUTSPLIT) {
                __nv_bfloat162 l0, l1;
                __nv_bfloat162 h0 = split_hi2(v0, v1, l0);
                __nv_bfloat162 h1 = split_hi2(v2, v3, l1);
                *(__nv_bfloat162*)(Chi + (long long)row * N + col) = h0;
                *(__nv_bfloat162*)(Chi + (long long)(row + 8) * N + col) = h1;
                *(__nv_bfloat162*)(Clo + (long long)row * N + col) = l0;
                *(__nv_bfloat162*)(Clo + (long long)(row + 8) * N + col) = l1;
            } else {
                float2 p0; p0.x = v0; p0.y = v1;
                float2 p1; p1.x = v2; p1.y = v3;
                *(float2*)(C + (long long)row * N + col) = p0;
                *(float2*)(C + (long long)(row + 8) * N + col) = p1;
            }
        }
    }
    if (STATS) {
#pragma unroll
        for (int ni = 0; ni < 8; ni++)
#pragma unroll
            for (int h = 0; h < 2; h++) {
                float s1 = cs1[ni][h], s2 = cs2[ni][h];
                s1 += __shfl_down_sync(0xffffffffu, s1, 16);
                s2 += __shfl_down_sync(0xffffffffu, s2, 16);
                s1 += __shfl_down_sync(0xffffffffu, s1, 8);
                s2 += __shfl_down_sync(0xffffffffu, s2, 8);
                s1 += __shfl_down_sync(0xffffffffu, s1, 4);
                s2 += __shfl_down_sync(0xffffffffu, s2, 4);
                if (lane < 4) {
                    int col = n0 + (wn << 6) + (ni << 3) + (lane << 1) + h;
                    atomicAdd(&g_s1[col], s1);
                    atomicAdd(&g_s2[col], s2);
                }
            }
    }
}

// ---------------------------------------------------------------------------
// vk split-K reduce -> hi/lo bf16 with alpha
// ---------------------------------------------------------------------------
__global__ void vkred_kernel()
{
    long long i4 = (long long)(blockIdx.x * 256 + threadIdx.x) * 4;
    int b = (int)(i4 >> 18);
    long long off = i4 & 262143;
    const float* p = g_vkp + ((long long)b * 4) * 262144 + off;
    float4 s0 = *(const float4*)p;
    float4 s1 = *(const float4*)(p + 262144);
    float4 s2 = *(const float4*)(p + 2 * 262144);
    float4 s3 = *(const float4*)(p + 3 * 262144);
    const float al = 1.f / 4096.f;
    float v0 = ((s0.x + s1.x) + (s2.x + s3.x)) * al;
    float v1 = ((s0.y + s1.y) + (s2.y + s3.y)) * al;
    float v2 = ((s0.z + s1.z) + (s2.z + s3.z)) * al;
    float v3 = ((s0.w + s1.w) + (s2.w + s3.w)) * al;
    __nv_bfloat162 l0, l1;
    __nv_bfloat162 h0 = split_hi2(v0, v1, l0);
    __nv_bfloat162 h1 = split_hi2(v2, v3, l1);
    *(__nv_bfloat162*)(g_vkhi + i4)     = h0;
    *(__nv_bfloat162*)(g_vkhi + i4 + 2) = h1;
    *(__nv_bfloat162*)(g_vklo + i4)     = l0;
    *(__nv_bfloat162*)(g_vklo + i4 + 2) = l1;
}

// ---------------------------------------------------------------------------
__global__ void zero_kernel()
{
    int i = blockIdx.x * 256 + threadIdx.x;
    if (i < 2048) { g_s1[i] = 0.f; g_s2[i] = 0.f; }
    if (i < 4096) g_ksum[i] = 0.f;
}

__global__ void bn1_finalize(const float* __restrict__ gamma,
                             const float* __restrict__ beta)
{
    int c = blockIdx.x * 256 + threadIdx.x;
    const float inv = 1.f / (BATCH * NPIX);
    float mean = g_s1[c] * inv;
    float var = g_s2[c] * inv - mean * mean;
    float av = gamma[c] * rsqrtf(var + 1e-5f);
    g_a1[c] = av;
    g_b1[c] = beta[c] - mean * av;
}

// q: sigmoid(affine(y[:, 0:512])) -> q^T hi/lo bf16
__global__ void q_kernel()
{
    int i = blockIdx.x * 256 + threadIdx.x;
    int r = i >> 7;
    int dg = (i & 127) << 2;
    long long yb = (long long)r * C4 + dg;
    __nv_bfloat162 yh0 = *(const __nv_bfloat162*)(g_ythi + yb);
    __nv_bfloat162 yh1 = *(const __nv_bfloat162*)(g_ythi + yb + 2);
    __nv_bfloat162 yl0 = *(const __nv_bfloat162*)(g_ytlo + yb);
    __nv_bfloat162 yl1 = *(const __nv_bfloat162*)(g_ytlo + yb + 2);
    float4 a4 = *(const float4*)(g_a1 + dg);
    float4 b4 = *(const float4*)(g_b1 + dg);
    float y0 = __bfloat162float(yh0.x) + __bfloat162float(yl0.x);
    float y1 = __bfloat162float(yh0.y) + __bfloat162float(yl0.y);
    float y2 = __bfloat162float(yh1.x) + __bfloat162float(yl1.x);
    float y3 = __bfloat162float(yh1.y) + __bfloat162float(yl1.y);
    float q0 = 1.f / (1.f + expf(-(a4.x * y0 + b4.x)));
    float q1 = 1.f / (1.f + expf(-(a4.y * y1 + b4.y)));
    float q2 = 1.f / (1.f + expf(-(a4.z * y2 + b4.z)));
    float q3 = 1.f / (1.f + expf(-(a4.w * y3 + b4.w)));
    __nv_bfloat162 l0, l1;
    __nv_bfloat162 h0 = split_hi2(q0, q1, l0);
    __nv_bfloat162 h1 = split_hi2(q2, q3, l1);
    long long o = (long long)r * DIM + dg;
    *(__nv_bfloat162*)(g_qthi + o)     = h0;
    *(__nv_bfloat162*)(g_qthi + o + 2) = h1;
    *(__nv_bfloat162*)(g_qtlo + o)     = l0;
    *(__nv_bfloat162*)(g_qtlo + o + 2) = l1;
}

// k,v: 64x64 transpose y^T -> [b][d][n] hi/lo bf16, sigmoid/affine, ksum
__global__ void kvt_kernel()
{
    __shared__ float tk[64][65], tv[64][65];
    int bz = blockIdx.z;
    int n0 = blockIdx.x << 6, d0 = blockIdx.y << 6;
    int tx = threadIdx.x, ty = threadIdx.y;
    int dloc = tx << 1;
    float2 akp = *(const float2*)(g_a1 + 512 + d0 + dloc);
    float2 bkp = *(const float2*)(g_b1 + 512 + d0 + dloc);
    float2 avp = *(const float2*)(g_a1 + 1024 + d0 + dloc);
    float2 bvp = *(const float2*)(g_b1 + 1024 + d0 + dloc);
#pragma unroll
    for (int i = 0; i < 8; i++) {
        int nl = ty + (i << 3);
        long long rb = ((long long)(bz << 12) + n0 + nl) * C4;
        __nv_bfloat162 kh2 = *(const __nv_bfloat162*)(g_ythi + rb + 512 + d0 + dloc);
        __nv_bfloat162 kl2 = *(const __nv_bfloat162*)(g_ytlo + rb + 512 + d0 + dloc);
        __nv_bfloat162 vh2 = *(const __nv_bfloat162*)(g_ythi + rb + 1024 + d0 + dloc);
        __nv_bfloat162 vl2 = *(const __nv_bfloat162*)(g_ytlo + rb + 1024 + d0 + dloc);
        float k0 = __bfloat162float(kh2.x) + __bfloat162float(kl2.x);
        float k1 = __bfloat162float(kh2.y) + __bfloat162float(kl2.y);
        float v0 = __bfloat162float(vh2.x) + __bfloat162float(vl2.x);
        float v1 = __bfloat162float(vh2.y) + __bfloat162float(vl2.y);
        tk[nl][dloc]     = 1.f / (1.f + expf(-(akp.x * k0 + bkp.x)));
        tk[nl][dloc + 1] = 1.f / (1.f + expf(-(akp.y * k1 + bkp.y)));
        tv[nl][dloc]     = avp.x * v0 + bvp.x;
        tv[nl][dloc + 1] = avp.y * v1 + bvp.y;
    }
    __syncthreads();
#pragma unroll
    for (int i = 0; i < 8; i++) {
        int dl = ty + (i << 3);
        int d = d0 + dl;
        int nl = tx << 1;
        float k0 = tk[nl][dl], k1 = tk[nl + 1][dl];
        float v0 = tv[nl][dl], v1 = tv[nl + 1][dl];
        long long o = ((long long)(bz << 9) + d) * NPIX + n0 + nl;
        __nv_bfloat162 kl2, vl2;
        __nv_bfloat162 kh2 = split_hi2(k0, k1, kl2);
        __nv_bfloat162 vh2 = split_hi2(v0, v1, vl2);
        *(__nv_bfloat162*)(g_khi + o) = kh2;
        *(__nv_bfloat162*)(g_klo + o) = kl2;
        *(__nv_bfloat162*)(g_vhi + o) = vh2;
        *(__nv_bfloat162*)(g_vlo + o) = vl2;
        float s = k0 + k1;
#pragma unroll
        for (int off = 16; off > 0; off >>= 1)
            s += __shfl_down_sync(0xffffffffu, s, off);
        if (tx == 0) atomicAdd(&g_ksum[(bz << 9) + d], s);
    }
}

// z[r] = sum_d kmean[d] * q[r][d] + eps
__global__ void z_kernel()
{
    __shared__ float km[512];
    int r0 = blockIdx.x << 3;
    int bb = r0 >> 12;
    for (int i = threadIdx.x; i < 512; i += 256)
        km[i] = g_ksum[(bb << 9) + i] * (1.f / NPIX);
    __syncthreads();
    int w = threadIdx.x >> 5, lane = threadIdx.x & 31;
    int r = r0 + w;
    const __nv_bfloat16* qh = g_qthi + (long long)r * DIM;
    const __nv_bfloat16* ql = g_qtlo + (long long)r * DIM;
    float s = 0.f;
#pragma unroll
    for (int i = 0; i < 16; i++) {
        int d = lane + (i << 5);
        s += km[d] * (__bfloat162float(qh[d]) + __bfloat162float(ql[d]));
    }
#pragma unroll
    for (int off = 16; off > 0; off >>= 1)
        s += __shfl_down_sync(0xffffffffu, s, off);
    if (lane == 0) g_z[r] = s + 5e-4f;
}

// RMSNorm row + anw + SiLU(gate) -> o^T hi/lo
__global__ void rmsgate_kernel(const float* __restrict__ anw)
{
    __shared__ float red[4];
    int r = blockIdx.x;
    int t = threadIdx.x;
    int dg = t << 2;
    long long arow = (long long)r * DIM + dg;
    __nv_bfloat162 ah0 = *(const __nv_bfloat162*)(g_athi + arow);
    __nv_bfloat162 ah1 = *(const __nv_bfloat162*)(g_athi + arow + 2);
    __nv_bfloat162 al0 = *(const __nv_bfloat162*)(g_atlo + arow);
    __nv_bfloat162 al1 = *(const __nv_bfloat162*)(g_atlo + arow + 2);
    float a0 = __bfloat162float(ah0.x) + __bfloat162float(al0.x);
    float a1 = __bfloat162float(ah0.y) + __bfloat162float(al0.y);
    float a2 = __bfloat162float(ah1.x) + __bfloat162float(al1.x);
    float a3 = __bfloat162float(ah1.y) + __bfloat162float(al1.y);
    float ss = a0 * a0 + a1 * a1 + a2 * a2 + a3 * a3;
    int lane = t & 31, w = t >> 5;
#pragma unroll
    for (int off = 16; off > 0; off >>= 1)
        ss += __shfl_down_sync(0xffffffffu, ss, off);
    if (lane == 0) red[w] = ss;
    __syncthreads();
    float tot = red[0] + red[1] + red[2] + red[3];
    float rms = rsqrtf(tot * (1.f / DIM) + 1e-6f);

    long long grow = (long long)r * C4 + 1536 + dg;
    __nv_bfloat162 gh0 = *(const __nv_bfloat162*)(g_ythi + grow);
    __nv_bfloat162 gh1 = *(const __nv_bfloat162*)(g_ythi + grow + 2);
    __nv_bfloat162 gl0 = *(const __nv_bfloat162*)(g_ytlo + grow);
    __nv_bfloat162 gl1 = *(const __nv_bfloat162*)(g_ytlo + grow + 2);
    float yg0 = __bfloat162float(gh0.x) + __bfloat162float(gl0.x);
    float yg1 = __bfloat162float(gh0.y) + __bfloat162float(gl0.y);
    float yg2 = __bfloat162float(gh1.x) + __bfloat162float(gl1.x);
    float yg3 = __bfloat162float(gh1.y) + __bfloat162float(gl1.y);
    float4 ga = *(const float4*)(g_a1 + 1536 + dg);
    float4 gb = *(const float4*)(g_b1 + 1536 + dg);
    float4 wn = *(const float4*)(anw + dg);
    float g0 = ga.x * yg0 + gb.x, g1 = ga.y * yg1 + gb.y;
    float g2 = ga.z * yg2 + gb.z, g3 = ga.w * yg3 + gb.w;
    float o0 = a0 * rms * wn.x * (g0 / (1.f + expf(-g0)));
    float o1 = a1 * rms * wn.y * (g1 / (1.f + expf(-g1)));
    float o2 = a2 * rms * wn.z * (g2 / (1.f + expf(-g2)));
    float o3 = a3 * rms * wn.w * (g3 / (1.f + expf(-g3)));
    __nv_bfloat162 l0, l1;
    __nv_bfloat162 h0 = split_hi2(o0, o1, l0);
    __nv_bfloat162 h1 = split_hi2(o2, o3, l1);
    long long o = (long long)r * DIM + dg;
    *(__nv_bfloat162*)(g_othi + o)     = h0;
    *(__nv_bfloat162*)(g_othi + o + 2) = h1;
    *(__nv_bfloat162*)(g_otlo + o)     = l0;
    *(__nv_bfloat162*)(g_otlo + o + 2) = l1;
}

__device__ __forceinline__ void blockReduce2(float& s1, float& s2)
{
    __shared__ float sh1[32], sh2[32];
    int lane = threadIdx.x & 31, w = threadIdx.x >> 5;
#pragma unroll
    for (int o = 16; o > 0; o >>= 1) {
        s1 += __shfl_down_sync(0xffffffffu, s1, o);
        s2 += __shfl_down_sync(0xffffffffu, s2, o);
    }
    if (lane == 0) { sh1[w] = s1; sh2[w] = s2; }
    __syncthreads();
    int nw = blockDim.x >> 5;
    if (w == 0) {
        s1 = lane < nw ? sh1[lane] : 0.f;
        s2 = lane < nw ? sh2[lane] : 0.f;
#pragma unroll
        for (int o = 16; o > 0; o >>= 1) {
            s1 += __shfl_down_sync(0xffffffffu, s1, o);
            s2 += __shfl_down_sync(0xffffffffu, s2, o);
        }
    }
}

__global__ void bn_stats_kernel(const float* __restrict__ y,
                                const float* __restrict__ gamma,
                                const float* __restrict__ beta,
                                float* __restrict__ a, float* __restrict__ bb,
                                int Cdim)
{
    int c = blockIdx.x;
    float s1 = 0.f, s2 = 0.f;
    for (int i = threadIdx.x; i < BATCH * NPIX; i += blockDim.x) {
        int bi = i >> 12, n = i & 4095;
        float v = y[((long long)bi * Cdim + c) * NPIX + n];
        s1 += v; s2 += v * v;
    }
    blockReduce2(s1, s2);
    if (threadIdx.x == 0) {
        const float inv = 1.f / (BATCH * NPIX);
        float mean = s1 * inv;
        float var = s2 * inv - mean * mean;
        float av = gamma[c] * rsqrtf(var + 1e-5f);
        a[c] = av;
        bb[c] = beta[c] - mean * av;
    }
}

__global__ void bnapply_kernel(float* __restrict__ out)
{
    long long i = (long long)(blockIdx.x * blockDim.x + threadIdx.x) * 4;
    int c = (int)((i >> 12) & 511);
    float a = g_a2[c], bb = g_b2[c];
    float4 v = *reinterpret_cast<const float4*>(g_ypre + i);
    v.x = a * v.x + bb; v.y = a * v.y + bb;
    v.z = a * v.z + bb; v.w = a * v.w + bb;
    *reinterpret_cast<float4*>(out + i) = v;
}

__global__ void convert_split(const float* __restrict__ s,
                              __nv_bfloat16* __restrict__ hi,
                              __nv_bfloat16* __restrict__ lo, int n)
{
    int i = blockIdx.x * blockDim.x + threadIdx.x;
    if (i < n) {
        float v = s[i];
        __nv_bfloat16 h = __float2bfloat16(v);
        hi[i] = h;
        lo[i] = __float2bfloat16(v - __bfloat162float(h));
    }
}

__global__ void transpose_split(const float* __restrict__ src,
                                __nv_bfloat16* __restrict__ dhi,
                                __nv_bfloat16* __restrict__ dlo, int R, int Cc)
{
    __shared__ float t[32][33];
    int b = blockIdx.z;
    long long o = (long long)b * R * Cc;
    src += o; dhi += o; dlo += o;
    int c0 = blockIdx.x * 32, r0 = blockIdx.y * 32;
    int tx = threadIdx.x, ty = threadIdx.y;
#pragma unroll
    for (int i = 0; i < 4; i++)
        t[ty + 8 * i][tx] = src[(long long)(r0 + ty + 8 * i) * Cc + c0 + tx];
    __syncthreads();
#pragma unroll
    for (int i = 0; i < 4; i++) {
        int cc = c0 + ty + 8 * i;
        float v = t[tx][ty + 8 * i];
        __nv_bfloat16 h = __float2bfloat16(v);
        dhi[(long long)cc * R + r0 + tx] = h;
        dlo[(long long)cc * R + r0 + tx] = __float2bfloat16(v - __bfloat162float(h));
    }
}

// ---------------------------------------------------------------------------
extern "C" void kernel_launch(void* const* d_in, const int* in_sizes, int n_in,
                              void* d_out, int out_size)
{
    const float* x           = (const float*)d_in[0];
    const float* qkvg_w      = (const float*)d_in[1];
    const float* qkvg_gamma  = (const float*)d_in[2];
    const float* qkvg_beta   = (const float*)d_in[3];
    const float* attn_norm_w = (const float*)d_in[4];
    const float* proj_w      = (const float*)d_in[5];
    const float* proj_gamma  = (const float*)d_in[6];
    const float* proj_beta   = (const float*)d_in[7];
    float* out = (float*)d_out;

    cudaFuncSetAttribute(gemm_mma<false, false, false>,
                         cudaFuncAttributeMaxDynamicSharedMemorySize, GSMEM);
    cudaFuncSetAttribute(gemm_mma<false, true, true>,
                         cudaFuncAttributeMaxDynamicSharedMemorySize, GSMEM);
    cudaFuncSetAttribute(gemm_mma<true, true, false>,
                         cudaFuncAttributeMaxDynamicSharedMemorySize, GSMEM);

    float *pypre, *pvkp, *pa2, *pb2, *pz;
    __nv_bfloat16 *pythi, *pytlo, *pathi, *patlo;
    __nv_bfloat16 *pkhi, *pklo, *pvhi, *pvlo, *pqthi, *pqtlo, *pxthi, *pxtlo;
    __nv_bfloat16 *pothi, *potlo, *pvkhi, *pvklo, *pwqhi, *pwqlo, *ppwhi, *ppwlo;
    cudaGetSymbolAddress((void**)&pythi, g_ythi);
    cudaGetSymbolAddress((void**)&pytlo, g_ytlo);
    cudaGetSymbolAddress((void**)&pathi, g_athi);
    cudaGetSymbolAddress((void**)&patlo, g_atlo);
    cudaGetSymbolAddress((void**)&pypre, g_ypre);
    cudaGetSymbolAddress((void**)&pvkp,  g_vkp);
    cudaGetSymbolAddress((void**)&pa2,   g_a2);
    cudaGetSymbolAddress((void**)&pb2,   g_b2);
    cudaGetSymbolAddress((void**)&pz,    g_z);
    cudaGetSymbolAddress((void**)&pkhi,  g_khi);
    cudaGetSymbolAddress((void**)&pklo,  g_klo);
    cudaGetSymbolAddress((void**)&pvhi,  g_vhi);
    cudaGetSymbolAddress((void**)&pvlo,  g_vlo);
    cudaGetSymbolAddress((void**)&pqthi, g_qthi);
    cudaGetSymbolAddress((void**)&pqtlo, g_qtlo);
    cudaGetSymbolAddress((void**)&pxthi, g_xthi);
    cudaGetSymbolAddress((void**)&pxtlo, g_xtlo);
    cudaGetSymbolAddress((void**)&pothi, g_othi);
    cudaGetSymbolAddress((void**)&potlo, g_otlo);
    cudaGetSymbolAddress((void**)&pvkhi, g_vkhi);
    cudaGetSymbolAddress((void**)&pvklo, g_vklo);
    cudaGetSymbolAddress((void**)&pwqhi, g_wqhi);
    cudaGetSymbolAddress((void**)&pwqlo, g_wqlo);
    cudaGetSymbolAddress((void**)&ppwhi, g_pwhi);
    cudaGetSymbolAddress((void**)&ppwlo, g_pwlo);

    const long long sQKV = (long long)DIM * NPIX;   // 2097152
    const long long sYT  = (long long)NPIX * C4;    // 8388608
    const long long sVK  = (long long)DIM * DIM;    // 262144

    zero_kernel<<<32, 256>>>();
    convert_split<<<4096, 256>>>(qkvg_w, pwqhi, pwqlo, C4 * DIM);
    convert_split<<<1024, 256>>>(proj_w, ppwhi, ppwlo, DIM * DIM);
    transpose_split<<<dim3(128, 16, BATCH), dim3(32, 8)>>>(x, pxthi, pxtlo, DIM, NPIX);

    // 1) y^T = x^T @ w^T -> bf16 hi/lo + fused BN1 column stats
    gemm_mma<false, true, true><<<dim3(16, 32, BATCH), 128, GSMEM>>>(
        pxthi, pxtlo, pwqhi, pwqlo, nullptr, pythi, pytlo,
        2048, 512, 512, 1, sQKV, 0, sYT, 1.f, nullptr);

    // 2) BN1 finalize
    bn1_finalize<<<8, 256>>>(qkvg_gamma, qkvg_beta);

    // 3) q^T hi/lo; k,v -> [d][n] hi/lo + ksum
    q_kernel<<<16384, 256>>>();
    kvt_kernel<<<dim3(64, 8, BATCH), dim3(32, 8)>>>();

    // 4) z
    z_kernel<<<4096, 256>>>();

    // 5) vk = v @ k^T, split-K x4; reduce -> hi/lo bf16
    gemm_mma<false, false, false><<<dim3(4, 4, BATCH * 4), 128, GSMEM>>>(
        pvhi, pvlo, pkhi, pklo, pvkp, nullptr, nullptr,
        512, 1024, 4096, 4, sQKV, sQKV, sVK, 1.f, nullptr);
    vkred_kernel<<<2048, 256>>>();

    // 6) attn^T = q^T @ vk^T / z -> hi/lo bf16
    gemm_mma<true, true, false><<<dim3(4, 32, BATCH), 128, GSMEM>>>(
        pqthi, pqtlo, pvkhi, pvklo, nullptr, pathi, patlo,
        512, 512, 512, 1, sQKV, sVK, sQKV, 1.f, pz);

    // 7) RMSNorm + gate -> o^T hi/lo
    rmsgate_kernel<<<32768, 128>>>(attn_norm_w);

    // 8) ypre = proj_w @ o
    gemm_mma<false, false, false><<<dim3(32, 4, BATCH), 128, GSMEM>>>(
        ppwhi, ppwlo, pothi, potlo, pypre, nullptr, nullptr,
        4096, 512, 512, 1, 0, sQKV, sQKV, 1.f, nullptr);

    // 9) BN2 + apply
    bn_stats_kernel<<<512, 256>>>(pypre, proj_gamma, proj_beta, pa2, pb2, 512);
    bnapply_kernel<<<16384, 256>>>(out);
}

// round 8
// speedup vs baseline: 2.3232x; 1.0506x over previous
#include <cuda_runtime.h>
#include <cuda_bf16.h>
#include <math.h>
#include <stdint.h>

// ---------------------------------------------------------------------------
// SHMA block: mma.sync bf16 GEMMs with FUSED 3-term hi/lo segments
// (fragment reuse: Ah shared by seg1/seg2, Bh shared by seg1/seg3),
// n-major dataflow, BN1 stats fused into GEMM1 epilogue.
// B=8, dim=d=512, N=4096, qkvg=2048.
// ---------------------------------------------------------------------------

#define BATCH 8
#define DIM   512
#define NPIX  4096
#define C4    2048

// ---------------- scratch (static device globals) --------------------------
__device__ __nv_bfloat16 g_ythi[67108864], g_ytlo[67108864]; // y^T (8*4096,2048)
__device__ __nv_bfloat16 g_athi[16777216], g_atlo[16777216]; // attn^T (8*4096,512)
__device__ float g_ypre[16777216];                   // ypre (8, 512, 4096) f32
__device__ float g_vkp[8388608];                     // vk split-K partials
__device__ __nv_bfloat16 g_khi[16777216], g_klo[16777216];   // k [b][d][n]
__device__ __nv_bfloat16 g_vhi[16777216], g_vlo[16777216];   // v [b][d][n]
__device__ __nv_bfloat16 g_qthi[16777216], g_qtlo[16777216]; // q^T [b][n][d]
__device__ __nv_bfloat16 g_xthi[16777216], g_xtlo[16777216]; // x^T [b][n][c]
__device__ __nv_bfloat16 g_othi[16777216], g_otlo[16777216]; // o^T [b][n][d]
__device__ __nv_bfloat16 g_vkhi[2097152], g_vklo[2097152];   // vk [b][d][e]
__device__ __nv_bfloat16 g_wqhi[1048576], g_wqlo[1048576];   // qkvg_w
__device__ __nv_bfloat16 g_pwhi[262144],  g_pwlo[262144];    // proj_w
__device__ float g_a1[2048], g_b1[2048], g_a2[512], g_b2[512];
__device__ float g_s1[2048], g_s2[2048];
__device__ float g_ksum[4096], g_z[32768];

// ---------------- helpers ---------------------------------------------------
__device__ __forceinline__ uint32_t smem_u32(const void* p) {
    uint32_t a;
    asm("{ .reg .u64 t; cvta.to.shared.u64 t, %1; cvt.u32.u64 %0, t; }"
        : "=r"(a) : "l"(p));
    return a;
}
__device__ __forceinline__ void ldsm_x4(uint32_t& r0, uint32_t& r1,
                                        uint32_t& r2, uint32_t& r3,
                                        uint32_t addr) {
    asm volatile("ldmatrix.sync.aligned.m8n8.x4.shared.b16 {%0,%1,%2,%3}, [%4];"
                 : "=r"(r0), "=r"(r1), "=r"(r2), "=r"(r3) : "r"(addr));
}
__device__ __forceinline__ void mma16816(float* c, const uint32_t* a,
                                         uint32_t b0, uint32_t b1) {
    asm volatile(
        "mma.sync.aligned.m16n8k16.row.col.f32.bf16.bf16.f32 "
        "{%0,%1,%2,%3}, {%4,%5,%6,%7}, {%8,%9}, {%0,%1,%2,%3};"
        : "+f"(c[0]), "+f"(c[1]), "+f"(c[2]), "+f"(c[3])
        : "r"(a[0]), "r"(a[1]), "r"(a[2]), "r"(a[3]), "r"(b0), "r"(b1));
}
__device__ __forceinline__ void cpasync16(uint32_t dst, const void* src) {
    asm volatile("cp.async.cg.shared.global [%0], [%1], 16;"
                 :: "r"(dst), "l"(src));
}
#define CP_COMMIT() asm volatile("cp.async.commit_group;" ::: "memory")
#define CP_WAIT(n)  asm volatile("cp.async.wait_group %0;" :: "n"(n) : "memory")

__device__ __forceinline__ __nv_bfloat162 split_hi2(float a, float b,
                                                    __nv_bfloat162& lo) {
    __nv_bfloat16 h0 = __float2bfloat16(a), h1 = __float2bfloat16(b);
    lo = __halves2bfloat162(__float2bfloat16(a - __bfloat162float(h0)),
                            __float2bfloat16(b - __bfloat162float(h1)));
    return __halves2bfloat162(h0, h1);
}

// ---------------------------------------------------------------------------
// mma.sync GEMM, fused 3-segment hi/lo: per 32-wide K-chunk all four tiles
// (Ah, Al, Bh, Bl) are staged; fragments of Ah reused for seg2 (Ah*Bl) and
// fragments of Bh reused for seg3 (Al*Bh). 128x128 CTA tile, 128 threads
// (2x2 warps, 64x64 warp tiles), 2-stage cp.async double buffer.
// Split-K via blockIdx.z = b*kchunks + ks (f32 C offset by zi*sC).
// ZDIV: row-divide by zb. OUTSPLIT: hi/lo bf16 out. STATS: per-column
// sum/sumsq atomics into g_s1/g_s2 (BN over columns).
// ---------------------------------------------------------------------------
#define SROW 40
#define BUFB (128 * SROW * 2)          // 10240 B per operand tile
#define STAGEB (4 * BUFB)              // Ah, Al, Bh, Bl
#define GSMEM (2 * STAGEB + 512)       // 2 stages + zsm

template <bool ZDIV, bool OUTSPLIT, bool STATS>
__global__ void __launch_bounds__(128)
gemm_mma(const __nv_bfloat16* __restrict__ Ahi_, const __nv_bfloat16* __restrict__ Alo_,
         const __nv_bfloat16* __restrict__ Bhi_, const __nv_bfloat16* __restrict__ Blo_,
         float* __restrict__ C_, __nv_bfloat16* __restrict__ Chi_,
         __nv_bfloat16* __restrict__ Clo_,
         int N, int K, int ldk, int kchunks,
         long long sA, long long sB, long long sC,
         float alpha, const float* __restrict__ zb)
{
    extern __shared__ char smem[];
    const int zi = blockIdx.z;
    const int b  = zi / kchunks;
    const int ks = zi - b * kchunks;
    const long long koff = (long long)ks * K;

    const __nv_bfloat16* Ah = Ahi_ + (long long)b * sA + koff;
    const __nv_bfloat16* Al = Alo_ + (long long)b * sA + koff;
    const __nv_bfloat16* Bh = Bhi_ + (long long)b * sB + koff;
    const __nv_bfloat16* Bl = Blo_ + (long long)b * sB + koff;
    const int m0 = blockIdx.y << 7, n0 = blockIdx.x << 7;
    const int tid = threadIdx.x, wid = tid >> 5, lane = tid & 31;
    const int wm = wid & 1, wn = wid >> 1;
    const int tig = lane & 3, grp = lane >> 2;

    const uint32_t sb = smem_u32(smem);
    float* zsm = (float*)(smem + 2 * STAGEB);
    if (ZDIV) zsm[tid] = 1.f / zb[(long long)b * 4096 + m0 + tid];

    const int CH = K >> 5;

    float acc[4][8][4];
#pragma unroll
    for (int i = 0; i < 4; i++)
#pragma unroll
        for (int j = 0; j < 8; j++)
#pragma unroll
            for (int t = 0; t < 4; t++) acc[i][j][t] = 0.f;

    // load all 4 operand tiles for K-chunk c into stage st
    auto load = [&](int c, int st) {
        long long kp = (long long)c << 5;
        uint32_t base = sb + (uint32_t)st * STAGEB;
#pragma unroll
        for (int i = 0; i < 4; i++) {
            int slot = tid + (i << 7);
            int row = slot >> 2, u = slot & 3;
            uint32_t d = (uint32_t)(row * (SROW * 2) + (u << 4));
            long long aoff = (long long)(m0 + row) * ldk + kp + (u << 3);
            long long boff = (long long)(n0 + row) * ldk + kp + (u << 3);
            cpasync16(base + d, Ah + aoff);
            cpasync16(base + BUFB + d, Al + aoff);
            cpasync16(base + 2 * BUFB + d, Bh + boff);
            cpasync16(base + 3 * BUFB + d, Bl + boff);
        }
        CP_COMMIT();
    };

    load(0, 0);

    const uint32_t lrow16 = lane & 15;
    const uint32_t lcol8 = (lane >> 4) << 3;

    int buf = 0;
    for (int c = 0; c < CH; c++) {
        if (c + 1 < CH) { load(c + 1, buf ^ 1); CP_WAIT(1); }
        else            { CP_WAIT(0); }
        __syncthreads();

        uint32_t base = sb + (uint32_t)buf * STAGEB;
#pragma unroll
        for (int ko2 = 0; ko2 < 2; ko2++) {
            const uint32_t ko = ko2 << 4;
            uint32_t ah[4][4], bh[4][4], tt[4][4];
#pragma unroll
            for (int mi = 0; mi < 4; mi++) {
                uint32_t ad = base +
                    (((wm << 6) + (mi << 4) + lrow16) * SROW + ko + lcol8) * 2;
                ldsm_x4(ah[mi][0], ah[mi][1], ah[mi][2], ah[mi][3], ad);
            }
#pragma unroll
            for (int nb = 0; nb < 4; nb++) {
                uint32_t bd = base + 2 * BUFB +
                    (((wn << 6) + (nb << 4) + lrow16) * SROW + ko + lcol8) * 2;
                ldsm_x4(bh[nb][0], bh[nb][1], bh[nb][2], bh[nb][3], bd);
            }
            // seg1: Ah * Bh
#pragma unroll
            for (int mi = 0; mi < 4; mi++)
#pragma unroll
                for (int ni = 0; ni < 8; ni++) {
                    int nb = ni >> 1, hf = ni & 1;
                    mma16816(acc[mi][ni], ah[mi], bh[nb][hf], bh[nb][hf + 2]);
                }
            // seg2: Ah * Bl (reuse ah fragments)
#pragma unroll
            for (int nb = 0; nb < 4; nb++) {
                uint32_t bd = base + 3 * BUFB +
                    (((wn << 6) + (nb << 4) + lrow16) * SROW + ko + lcol8) * 2;
                ldsm_x4(tt[nb][0], tt[nb][1], tt[nb][2], tt[nb][3], bd);
            }
#pragma unroll
            for (int mi = 0; mi < 4; mi++)
#pragma unroll
                for (int ni = 0; ni < 8; ni++) {
                    int nb = ni >> 1, hf = ni & 1;
                    mma16816(acc[mi][ni], ah[mi], tt[nb][hf], tt[nb][hf + 2]);
                }
            // seg3: Al * Bh (reuse bh fragments)
#pragma unroll
            for (int mi = 0; mi < 4; mi++) {
                uint32_t ad = base + BUFB +
                    (((wm << 6) + (mi << 4) + lrow16) * SROW + ko + lcol8) * 2;
                ldsm_x4(tt[mi][0], tt[mi][1], tt[mi][2], tt[mi][3], ad);
            }
#pragma unroll
            for (int mi = 0; mi < 4; mi++)
#pragma unroll
                for (int ni = 0; ni < 8; ni++) {
                    int nb = ni >> 1, hf = ni & 1;
                    mma16816(acc[mi][ni], tt[mi], bh[nb][hf], bh[nb][hf + 2]);
                }
        }
        __syncthreads();
        buf ^= 1;
    }

    // epilogue
    float* C = C_ + (long long)zi * sC;
    __nv_bfloat16* Chi = Chi_ + (long long)b * sC;
    __nv_bfloat16* Clo = Clo_ + (long long)b * sC;
    float cs1[8][2], cs2[8][2];
    if (STATS) {
#pragma unroll
        for (int ni = 0; ni < 8; ni++) {
            cs1[ni][0] = cs1[ni][1] = 0.f;
            cs2[ni][0] = cs2[ni][1] = 0.f;
        }
    }
#pragma unroll
    for (int mi = 0; mi < 4; mi++) {
        int rl = (wm << 6) + (mi << 4) + grp;
        int row = m0 + rl;
        float zr0 = 1.f, zr1 = 1.f;
        if (ZDIV) { zr0 = zsm[rl]; zr1 = zsm[rl + 8]; }
#pragma unroll
        for (int ni = 0; ni < 8; ni++) {
            int col = n0 + (wn << 6) + (ni << 3) + (tig << 1);
            float v0 = acc[mi][ni][0] * alpha;
            float v1 = acc[mi][ni][1] * alpha;
            float v2 = acc[mi][ni][2] * alpha;
            float v3 = acc[mi][ni][3] * alpha;
            if (ZDIV) { v0 *= zr0; v1 *= zr0; v2 *= zr1; v3 *= zr1; }
            if (STATS) {
                cs1[ni][0] += v0 + v2;
                cs1[ni][1] += v1 + v3;
                cs2[ni][0] += v0 * v0 + v2 * v2;
                cs2[ni][1] += v1 * v1 + v3 * v3;
            }
            if (OUTSPLIT) {
                __nv_bfloat162 l0, l1;
                __nv_bfloat162 h0 = split_hi2(v0, v1, l0);
                __nv_bfloat162 h1 = split_hi2(v2, v3, l1);
                *(__nv_bfloat162*)(Chi + (long long)row * N + col) = h0;
                *(__nv_bfloat162*)(Chi + (long long)(row + 8) * N + col) = h1;
                *(__nv_bfloat162*)(Clo + (long long)row * N + col) = l0;
                *(__nv_bfloat162*)(Clo + (long long)(row + 8) * N + col) = l1;
            } else {
                float2 p0; p0.x = v0; p0.y = v1;
                float2 p1; p1.x = v2; p1.y = v3;
                *(float2*)(C + (long long)row * N + col) = p0;
                *(float2*)(C + (long long)(row + 8) * N + col) = p1;
            }
        }
    }
    if (STATS) {
#pragma unroll
        for (int ni = 0; ni < 8; ni++)
#pragma unroll
            for (int h = 0; h < 2; h++) {
                float s1 = cs1[ni][h], s2 = cs2[ni][h];
                s1 += __shfl_down_sync(0xffffffffu, s1, 16);
                s2 += __shfl_down_sync(0xffffffffu, s2, 16);
                s1 += __shfl_down_sync(0xffffffffu, s1, 8);
                s2 += __shfl_down_sync(0xffffffffu, s2, 8);
                s1 += __shfl_down_sync(0xffffffffu, s1, 4);
                s2 += __shfl_down_sync(0xffffffffu, s2, 4);
                if (lane < 4) {
                    int col = n0 + (wn << 6) + (ni << 3) + (lane << 1) + h;
                    atomicAdd(&g_s1[col], s1);
                    atomicAdd(&g_s2[col], s2);
                }
            }
    }
}

// ---------------------------------------------------------------------------
// vk split-K reduce -> hi/lo bf16 with alpha
// ---------------------------------------------------------------------------
__global__ void vkred_kernel()
{
    long long i4 = (long long)(blockIdx.x * 256 + threadIdx.x) * 4;
    int b = (int)(i4 >> 18);
    long long off = i4 & 262143;
    const float* p = g_vkp + ((long long)b * 4) * 262144 + off;
    float4 s0 = *(const float4*)p;
    float4 s1 = *(const float4*)(p + 262144);
    float4 s2 = *(const float4*)(p + 2 * 262144);
    float4 s3 = *(const float4*)(p + 3 * 262144);
    const float al = 1.f / 4096.f;
    float v0 = ((s0.x + s1.x) + (s2.x + s3.x)) * al;
    float v1 = ((s0.y + s1.y) + (s2.y + s3.y)) * al;
    float v2 = ((s0.z + s1.z) + (s2.z + s3.z)) * al;
    float v3 = ((s0.w + s1.w) + (s2.w + s3.w)) * al;
    __nv_bfloat162 l0, l1;
    __nv_bfloat162 h0 = split_hi2(v0, v1, l0);
    __nv_bfloat162 h1 = split_hi2(v2, v3, l1);
    *(__nv_bfloat162*)(g_vkhi + i4)     = h0;
    *(__nv_bfloat162*)(g_vkhi + i4 + 2) = h1;
    *(__nv_bfloat162*)(g_vklo + i4)     = l0;
    *(__nv_bfloat162*)(g_vklo + i4 + 2) = l1;
}

// ---------------------------------------------------------------------------
__global__ void zero_kernel()
{
    int i = blockIdx.x * 256 + threadIdx.x;
    if (i < 2048) { g_s1[i] = 0.f; g_s2[i] = 0.f; }
    if (i < 4096) g_ksum[i] = 0.f;
}

__global__ void bn1_finalize(const float* __restrict__ gamma,
                             const float* __restrict__ beta)
{
    int c = blockIdx.x * 256 + threadIdx.x;
    const float inv = 1.f / (BATCH * NPIX);
    float mean = g_s1[c] * inv;
    float var = g_s2[c] * inv - mean * mean;
    float av = gamma[c] * rsqrtf(var + 1e-5f);
    g_a1[c] = av;
    g_b1[c] = beta[c] - mean * av;
}

// q: sigmoid(affine(y[:, 0:512])) -> q^T hi/lo bf16
__global__ void q_kernel()
{
    int i = blockIdx.x * 256 + threadIdx.x;
    int r = i >> 7;
    int dg = (i & 127) << 2;
    long long yb = (long long)r * C4 + dg;
    __nv_bfloat162 yh0 = *(const __nv_bfloat162*)(g_ythi + yb);
    __nv_bfloat162 yh1 = *(const __nv_bfloat162*)(g_ythi + yb + 2);
    __nv_bfloat162 yl0 = *(const __nv_bfloat162*)(g_ytlo + yb);
    __nv_bfloat162 yl1 = *(const __nv_bfloat162*)(g_ytlo + yb + 2);
    float4 a4 = *(const float4*)(g_a1 + dg);
    float4 b4 = *(const float4*)(g_b1 + dg);
    float y0 = __bfloat162float(yh0.x) + __bfloat162float(yl0.x);
    float y1 = __bfloat162float(yh0.y) + __bfloat162float(yl0.y);
    float y2 = __bfloat162float(yh1.x) + __bfloat162float(yl1.x);
    float y3 = __bfloat162float(yh1.y) + __bfloat162float(yl1.y);
    float q0 = 1.f / (1.f + expf(-(a4.x * y0 + b4.x)));
    float q1 = 1.f / (1.f + expf(-(a4.y * y1 + b4.y)));
    float q2 = 1.f / (1.f + expf(-(a4.z * y2 + b4.z)));
    float q3 = 1.f / (1.f + expf(-(a4.w * y3 + b4.w)));
    __nv_bfloat162 l0, l1;
    __nv_bfloat162 h0 = split_hi2(q0, q1, l0);
    __nv_bfloat162 h1 = split_hi2(q2, q3, l1);
    long long o = (long long)r * DIM + dg;
    *(__nv_bfloat162*)(g_qthi + o)     = h0;
    *(__nv_bfloat162*)(g_qthi + o + 2) = h1;
    *(__nv_bfloat162*)(g_qtlo + o)     = l0;
    *(__nv_bfloat162*)(g_qtlo + o + 2) = l1;
}

// k,v: 64x64 transpose y^T -> [b][d][n] hi/lo bf16, sigmoid/affine, ksum
__global__ void kvt_kernel()
{
    __shared__ float tk[64][65], tv[64][65];
    int bz = blockIdx.z;
    int n0 = blockIdx.x << 6, d0 = blockIdx.y << 6;
    int tx = threadIdx.x, ty = threadIdx.y;
    int dloc = tx << 1;
    float2 akp = *(const float2*)(g_a1 + 512 + d0 + dloc);
    float2 bkp = *(const float2*)(g_b1 + 512 + d0 + dloc);
    float2 avp = *(const float2*)(g_a1 + 1024 + d0 + dloc);
    float2 bvp = *(const float2*)(g_b1 + 1024 + d0 + dloc);
#pragma unroll
    for (int i = 0; i < 8; i++) {
        int nl = ty + (i << 3);
        long long rb = ((long long)(bz << 12) + n0 + nl) * C4;
        __nv_bfloat162 kh2 = *(const __nv_bfloat162*)(g_ythi + rb + 512 + d0 + dloc);
        __nv_bfloat162 kl2 = *(const __nv_bfloat162*)(g_ytlo + rb + 512 + d0 + dloc);
        __nv_bfloat162 vh2 = *(const __nv_bfloat162*)(g_ythi + rb + 1024 + d0 + dloc);
        __nv_bfloat162 vl2 = *(const __nv_bfloat162*)(g_ytlo + rb + 1024 + d0 + dloc);
        float k0 = __bfloat162float(kh2.x) + __bfloat162float(kl2.x);
        float k1 = __bfloat162float(kh2.y) + __bfloat162float(kl2.y);
        float v0 = __bfloat162float(vh2.x) + __bfloat162float(vl2.x);
        float v1 = __bfloat162float(vh2.y) + __bfloat162float(vl2.y);
        tk[nl][dloc]     = 1.f / (1.f + expf(-(akp.x * k0 + bkp.x)));
        tk[nl][dloc + 1] = 1.f / (1.f + expf(-(akp.y * k1 + bkp.y)));
        tv[nl][dloc]     = avp.x * v0 + bvp.x;
        tv[nl][dloc + 1] = avp.y * v1 + bvp.y;
    }
    __syncthreads();
#pragma unroll
    for (int i = 0; i < 8; i++) {
        int dl = ty + (i << 3);
        int d = d0 + dl;
        int nl = tx << 1;
        float k0 = tk[nl][dl], k1 = tk[nl + 1][dl];
        float v0 = tv[nl][dl], v1 = tv[nl + 1][dl];
        long long o = ((long long)(bz << 9) + d) * NPIX + n0 + nl;
        __nv_bfloat162 kl2, vl2;
        __nv_bfloat162 kh2 = split_hi2(k0, k1, kl2);
        __nv_bfloat162 vh2 = split_hi2(v0, v1, vl2);
        *(__nv_bfloat162*)(g_khi + o) = kh2;
        *(__nv_bfloat162*)(g_klo + o) = kl2;
        *(__nv_bfloat162*)(g_vhi + o) = vh2;
        *(__nv_bfloat162*)(g_vlo + o) = vl2;
        float s = k0 + k1;
#pragma unroll
        for (int off = 16; off > 0; off >>= 1)
            s += __shfl_down_sync(0xffffffffu, s, off);
        if (tx == 0) atomicAdd(&g_ksum[(bz << 9) + d], s);
    }
}

// z[r] = sum_d kmean[d] * q[r][d] + eps
__global__ void z_kernel()
{
    __shared__ float km[512];
    int r0 = blockIdx.x << 3;
    int bb = r0 >> 12;
    for (int i = threadIdx.x; i < 512; i += 256)
        km[i] = g_ksum[(bb << 9) + i] * (1.f / NPIX);
    __syncthreads();
    int w = threadIdx.x >> 5, lane = threadIdx.x & 31;
    int r = r0 + w;
    const __nv_bfloat16* qh = g_qthi + (long long)r * DIM;
    const __nv_bfloat16* ql = g_qtlo + (long long)r * DIM;
    float s = 0.f;
#pragma unroll
    for (int i = 0; i < 16; i++) {
        int d = lane + (i << 5);
        s += km[d] * (__bfloat162float(qh[d]) + __bfloat162float(ql[d]));
    }
#pragma unroll
    for (int off = 16; off > 0; off >>= 1)
        s += __shfl_down_sync(0xffffffffu, s, off);
    if (lane == 0) g_z[r] = s + 5e-4f;
}

// RMSNorm row + anw + SiLU(gate) -> o^T hi/lo
__global__ void rmsgate_kernel(const float* __restrict__ anw)
{
    __shared__ float red[4];
    int r = blockIdx.x;
    int t = threadIdx.x;
    int dg = t << 2;
    long long arow = (long long)r * DIM + dg;
    __nv_bfloat162 ah0 = *(const __nv_bfloat162*)(g_athi + arow);
    __nv_bfloat162 ah1 = *(const __nv_bfloat162*)(g_athi + arow + 2);
    __nv_bfloat162 al0 = *(const __nv_bfloat162*)(g_atlo + arow);
    __nv_bfloat162 al1 = *(const __nv_bfloat162*)(g_atlo + arow + 2);
    float a0 = __bfloat162float(ah0.x) + __bfloat162float(al0.x);
    float a1 = __bfloat162float(ah0.y) + __bfloat162float(al0.y);
    float a2 = __bfloat162float(ah1.x) + __bfloat162float(al1.x);
    float a3 = __bfloat162float(ah1.y) + __bfloat162float(al1.y);
    float ss = a0 * a0 + a1 * a1 + a2 * a2 + a3 * a3;
    int lane = t & 31, w = t >> 5;
#pragma unroll
    for (int off = 16; off > 0; off >>= 1)
        ss += __shfl_down_sync(0xffffffffu, ss, off);
    if (lane == 0) red[w] = ss;
    __syncthreads();
    float tot = red[0] + red[1] + red[2] + red[3];
    float rms = rsqrtf(tot * (1.f / DIM) + 1e-6f);

    long long grow = (long long)r * C4 + 1536 + dg;
    __nv_bfloat162 gh0 = *(const __nv_bfloat162*)(g_ythi + grow);
    __nv_bfloat162 gh1 = *(const __nv_bfloat162*)(g_ythi + grow + 2);
    __nv_bfloat162 gl0 = *(const __nv_bfloat162*)(g_ytlo + grow);
    __nv_bfloat162 gl1 = *(const __nv_bfloat162*)(g_ytlo + grow + 2);
    float yg0 = __bfloat162float(gh0.x) + __bfloat162float(gl0.x);
    float yg1 = __bfloat162float(gh0.y) + __bfloat162float(gl0.y);
    float yg2 = __bfloat162float(gh1.x) + __bfloat162float(gl1.x);
    float yg3 = __bfloat162float(gh1.y) + __bfloat162float(gl1.y);
    float4 ga = *(const float4*)(g_a1 + 1536 + dg);
    float4 gb = *(const float4*)(g_b1 + 1536 + dg);
    float4 wn = *(const float4*)(anw + dg);
    float g0 = ga.x * yg0 + gb.x, g1 = ga.y * yg1 + gb.y;
    float g2 = ga.z * yg2 + gb.z, g3 = ga.w * yg3 + gb.w;
    float o0 = a0 * rms * wn.x * (g0 / (1.f + expf(-g0)));
    float o1 = a1 * rms * wn.y * (g1 / (1.f + expf(-g1)));
    float o2 = a2 * rms * wn.z * (g2 / (1.f + expf(-g2)));
    float o3 = a3 * rms * wn.w * (g3 / (1.f + expf(-g3)));
    __nv_bfloat162 l0, l1;
    __nv_bfloat162 h0 = split_hi2(o0, o1, l0);
    __nv_bfloat162 h1 = split_hi2(o2, o3, l1);
    long long o = (long long)r * DIM + dg;
    *(__nv_bfloat162*)(g_othi + o)     = h0;
    *(__nv_bfloat162*)(g_othi + o + 2) = h1;
    *(__nv_bfloat162*)(g_otlo + o)     = l0;
    *(__nv_bfloat162*)(g_otlo + o + 2) = l1;
}

__device__ __forceinline__ void blockReduce2(float& s1, float& s2)
{
    __shared__ float sh1[32], sh2[32];
    int lane = threadIdx.x & 31, w = threadIdx.x >> 5;
#pragma unroll
    for (int o = 16; o > 0; o >>= 1) {
        s1 += __shfl_down_sync(0xffffffffu, s1, o);
        s2 += __shfl_down_sync(0xffffffffu, s2, o);
    }
    if (lane == 0) { sh1[w] = s1; sh2[w] = s2; }
    __syncthreads();
    int nw = blockDim.x >> 5;
    if (w == 0) {
        s1 = lane < nw ? sh1[lane] : 0.f;
        s2 = lane < nw ? sh2[lane] : 0.f;
#pragma unroll
        for (int o = 16; o > 0; o >>= 1) {
            s1 += __shfl_down_sync(0xffffffffu, s1, o);
            s2 += __shfl_down_sync(0xffffffffu, s2, o);
        }
    }
}

__global__ void bn_stats_kernel(const float* __restrict__ y,
                                const float* __restrict__ gamma,
                                const float* __restrict__ beta,
                                float* __restrict__ a, float* __restrict__ bb,
                                int Cdim)
{
    int c = blockIdx.x;
    float s1 = 0.f, s2 = 0.f;
    for (int i = threadIdx.x; i < BATCH * NPIX; i += blockDim.x) {
        int bi = i >> 12, n = i & 4095;
        float v = y[((long long)bi * Cdim + c) * NPIX + n];
        s1 += v; s2 += v * v;
    }
    blockReduce2(s1, s2);
    if (threadIdx.x == 0) {
        const float inv = 1.f / (BATCH * NPIX);
        float mean = s1 * inv;
        float var = s2 * inv - mean * mean;
        float av = gamma[c] * rsqrtf(var + 1e-5f);
        a[c] = av;
        bb[c] = beta[c] - mean * av;
    }
}

__global__ void bnapply_kernel(float* __restrict__ out)
{
    long long i = (long long)(blockIdx.x * blockDim.x + threadIdx.x) * 4;
    int c = (int)((i >> 12) & 511);
    float a = g_a2[c], bb = g_b2[c];
    float4 v = *reinterpret_cast<const float4*>(g_ypre + i);
    v.x = a * v.x + bb; v.y = a * v.y + bb;
    v.z = a * v.z + bb; v.w = a * v.w + bb;
    *reinterpret_cast<float4*>(out + i) = v;
}

__global__ void convert_split(const float* __restrict__ s,
                              __nv_bfloat16* __restrict__ hi,
                              __nv_bfloat16* __restrict__ lo, int n)
{
    int i = blockIdx.x * blockDim.x + threadIdx.x;
    if (i < n) {
        float v = s[i];
        __nv_bfloat16 h = __float2bfloat16(v);
        hi[i] = h;
        lo[i] = __float2bfloat16(v - __bfloat162float(h));
    }
}

__global__ void transpose_split(const float* __restrict__ src,
                                __nv_bfloat16* __restrict__ dhi,
                                __nv_bfloat16* __restrict__ dlo, int R, int Cc)
{
    __shared__ float t[32][33];
    int b = blockIdx.z;
    long long o = (long long)b * R * Cc;
    src += o; dhi += o; dlo += o;
    int c0 = blockIdx.x * 32, r0 = blockIdx.y * 32;
    int tx = threadIdx.x, ty = threadIdx.y;
#pragma unroll
    for (int i = 0; i < 4; i++)
        t[ty + 8 * i][tx] = src[(long long)(r0 + ty + 8 * i) * Cc + c0 + tx];
    __syncthreads();
#pragma unroll
    for (int i = 0; i < 4; i++) {
        int cc = c0 + ty + 8 * i;
        float v = t[tx][ty + 8 * i];
        __nv_bfloat16 h = __float2bfloat16(v);
        dhi[(long long)cc * R + r0 + tx] = h;
        dlo[(long long)cc * R + r0 + tx] = __float2bfloat16(v - __bfloat162float(h));
    }
}

// ---------------------------------------------------------------------------
extern "C" void kernel_launch(void* const* d_in, const int* in_sizes, int n_in,
                              void* d_out, int out_size)
{
    const float* x           = (const float*)d_in[0];
    const float* qkvg_w      = (const float*)d_in[1];
    const float* qkvg_gamma  = (const float*)d_in[2];
    const float* qkvg_beta   = (const float*)d_in[3];
    const float* attn_norm_w = (const float*)d_in[4];
    const float* proj_w      = (const float*)d_in[5];
    const float* proj_gamma  = (const float*)d_in[6];
    const float* proj_beta   = (const float*)d_in[7];
    float* out = (float*)d_out;

    cudaFuncSetAttribute(gemm_mma<false, false, false>,
                         cudaFuncAttributeMaxDynamicSharedMemorySize, GSMEM);
    cudaFuncSetAttribute(gemm_mma<false, true, true>,
                         cudaFuncAttributeMaxDynamicSharedMemorySize, GSMEM);
    cudaFuncSetAttribute(gemm_mma<true, true, false>,
                         cudaFuncAttributeMaxDynamicSharedMemorySize, GSMEM);

    float *pypre, *pvkp, *pa2, *pb2, *pz;
    __nv_bfloat16 *pythi, *pytlo, *pathi, *patlo;
    __nv_bfloat16 *pkhi, *pklo, *pvhi, *pvlo, *pqthi, *pqtlo, *pxthi, *pxtlo;
    __nv_bfloat16 *pothi, *potlo, *pvkhi, *pvklo, *pwqhi, *pwqlo, *ppwhi, *ppwlo;
    cudaGetSymbolAddress((void**)&pythi, g_ythi);
    cudaGetSymbolAddress((void**)&pytlo, g_ytlo);
    cudaGetSymbolAddress((void**)&pathi, g_athi);
    cudaGetSymbolAddress((void**)&patlo, g_atlo);
    cudaGetSymbolAddress((void**)&pypre, g_ypre);
    cudaGetSymbolAddress((void**)&pvkp,  g_vkp);
    cudaGetSymbolAddress((void**)&pa2,   g_a2);
    cudaGetSymbolAddress((void**)&pb2,   g_b2);
    cudaGetSymbolAddress((void**)&pz,    g_z);
    cudaGetSymbolAddress((void**)&pkhi,  g_khi);
    cudaGetSymbolAddress((void**)&pklo,  g_klo);
    cudaGetSymbolAddress((void**)&pvhi,  g_vhi);
    cudaGetSymbolAddress((void**)&pvlo,  g_vlo);
    cudaGetSymbolAddress((void**)&pqthi, g_qthi);
    cudaGetSymbolAddress((void**)&pqtlo, g_qtlo);
    cudaGetSymbolAddress((void**)&pxthi, g_xthi);
    cudaGetSymbolAddress((void**)&pxtlo, g_xtlo);
    cudaGetSymbolAddress((void**)&pothi, g_othi);
    cudaGetSymbolAddress((void**)&potlo, g_otlo);
    cudaGetSymbolAddress((void**)&pvkhi, g_vkhi);
    cudaGetSymbolAddress((void**)&pvklo, g_vklo);
    cudaGetSymbolAddress((void**)&pwqhi, g_wqhi);
    cudaGetSymbolAddress((void**)&pwqlo, g_wqlo);
    cudaGetSymbolAddress((void**)&ppwhi, g_pwhi);
    cudaGetSymbolAddress((void**)&ppwlo, g_pwlo);

    const long long sQKV = (long long)DIM * NPIX;   // 2097152
    const long long sYT  = (long long)NPIX * C4;    // 8388608
    const long long sVK  = (long long)DIM * DIM;    // 262144

    zero_kernel<<<32, 256>>>();
    convert_split<<<4096, 256>>>(qkvg_w, pwqhi, pwqlo, C4 * DIM);
    convert_split<<<1024, 256>>>(proj_w, ppwhi, ppwlo, DIM * DIM);
    transpose_split<<<dim3(128, 16, BATCH), dim3(32, 8)>>>(x, pxthi, pxtlo, DIM, NPIX);

    // 1) y^T = x^T @ w^T -> bf16 hi/lo + fused BN1 column stats
    gemm_mma<false, true, true><<<dim3(16, 32, BATCH), 128, GSMEM>>>(
        pxthi, pxtlo, pwqhi, pwqlo, nullptr, pythi, pytlo,
        2048, 512, 512, 1, sQKV, 0, sYT, 1.f, nullptr);

    // 2) BN1 finalize
    bn1_finalize<<<8, 256>>>(qkvg_gamma, qkvg_beta);

    // 3) q^T hi/lo; k,v -> [d][n] hi/lo + ksum
    q_kernel<<<16384, 256>>>();
    kvt_kernel<<<dim3(64, 8, BATCH), dim3(32, 8)>>>();

    // 4) z
    z_kernel<<<4096, 256>>>();

    // 5) vk = v @ k^T, split-K x4; reduce -> hi/lo bf16
    gemm_mma<false, false, false><<<dim3(4, 4, BATCH * 4), 128, GSMEM>>>(
        pvhi, pvlo, pkhi, pklo, pvkp, nullptr, nullptr,
        512, 1024, 4096, 4, sQKV, sQKV, sVK, 1.f, nullptr);
    vkred_kernel<<<2048, 256>>>();

    // 6) attn^T = q^T @ vk^T / z -> hi/lo bf16
    gemm_mma<true, true, false><<<dim3(4, 32, BATCH), 128, GSMEM>>>(
        pqthi, pqtlo, pvkhi, pvklo, nullptr, pathi, patlo,
        512, 512, 512, 1, sQKV, sVK, sQKV, 1.f, pz);

    // 7) RMSNorm + gate -> o^T hi/lo
    rmsgate_kernel<<<32768, 128>>>(attn_norm_w);

    // 8) ypre = proj_w @ o
    gemm_mma<false, false, false><<<dim3(32, 4, BATCH), 128, GSMEM>>>(
        ppwhi, ppwlo, pothi, potlo, pypre, nullptr, nullptr,
        4096, 512, 512, 1, 0, sQKV, sQKV, 1.f, nullptr);

    // 9) BN2 + apply
    bn_stats_kernel<<<512, 256>>>(pypre, proj_gamma, proj_beta, pa2, pb2, 512);
    bnapply_kernel<<<16384, 256>>>(out);
}